// round 6
// baseline (speedup 1.0000x reference)
#include <cuda_runtime.h>
#include <math.h>
#include <stdint.h>

#define BB 8
#define NN 8192
#define SS 2048
#define NSAMP 32
#define NSAMPLES (BB*SS*NSAMP)   /* 524288 */
#define NGROUPS (BB*SS)          /* 16384  */
#define NTILES (NSAMPLES/128)    /* 4096   */
#define R2 0.04f
#define BNEPS 1e-5f

typedef unsigned long long ull;

// ---------------- device scratch ----------------
__device__ float g_feat[(size_t)NSAMPLES*8];     // [sample][8] (6 used)
__device__ float g_gmax[(size_t)NGROUPS*128];
__device__ float g_gmin[(size_t)NGROUPS*128];
__device__ float g_fsum[6];
__device__ float g_fmom[21];
__device__ float g_M[64*64];                     // sum over samples of h1 h1^T
__device__ float g_h1sum[64];
__device__ float g_x3sum[128], g_x3sq[128];
__device__ float g_W1s[64*6], g_b1s[64];         // BN1 folded into W1 (written by k_bn2)
__device__ float g_sc2[64], g_sh2[64];

// ---------------- f32x2 helpers ----------------
static __device__ __forceinline__ void fma2(ull& d, ull a, ull b) {
    asm("fma.rn.f32x2 %0, %1, %2, %0;" : "+l"(d) : "l"(a), "l"(b));
}
static __device__ __forceinline__ float hadd2(ull v) {
    float lo, hi;
    asm("mov.b64 {%0,%1}, %2;" : "=f"(lo), "=f"(hi) : "l"(v));
    return lo + hi;
}

// ---------------- K0: zero accumulators ----------------
__global__ void k_zero() {
    int t = threadIdx.x;
    for (int i = t; i < 4096; i += 256) g_M[i] = 0.f;
    if (t < 6)  g_fsum[t] = 0.f;
    if (t < 21) g_fmom[t] = 0.f;
    if (t < 64) g_h1sum[t] = 0.f;
    if (t < 128){ g_x3sum[t] = 0.f; g_x3sq[t] = 0.f; }
}

// ---------------- K1: ball query + feat + feat moments + out1 ----------------
__global__ __launch_bounds__(256) void k_ball(const float* __restrict__ xyz,
                                              const float* __restrict__ points,
                                              const int*   __restrict__ fps,
                                              float* __restrict__ out1) {
    extern __shared__ float sm[];
    float* sx = sm;
    float* sy = sm + NN;
    float* sz = sm + 2*NN;
    int*   fnd = (int*)(sm + 3*NN);   // [8 warps][32]

    int b = blockIdx.y;
    int qbase = blockIdx.x * 32;
    int tid = threadIdx.x;

    for (int i = tid; i < NN; i += 256) {
        sx[i] = xyz[(b*3+0)*NN + i];
        sy[i] = xyz[(b*3+1)*NN + i];
        sz[i] = xyz[(b*3+2)*NN + i];
    }
    __syncthreads();

    int w = tid >> 5, lane = tid & 31;
    int* f = fnd + w*32;
    unsigned lmask = (1u << lane) - 1u;

    float s1[6], s2[21];
    #pragma unroll
    for (int i = 0; i < 6; i++)  s1[i] = 0.f;
    #pragma unroll
    for (int i = 0; i < 21; i++) s2[i] = 0.f;

    for (int qi = 0; qi < 4; qi++) {
        int s = qbase + w*4 + qi;
        int cidx = fps[b*SS + s];
        float cx = sx[cidx], cy = sy[cidx], cz = sz[cidx];
        if (lane == 0) {
            out1[(b*3+0)*SS + s] = cx;
            out1[(b*3+1)*SS + s] = cy;
            out1[(b*3+2)*SS + s] = cz;
        }
        int cnt = 0;
        for (int chunk = 0; chunk < NN/32; chunk++) {
            int j = chunk*32 + lane;
            float dx = __fsub_rn(sx[j], cx);
            float dy = __fsub_rn(sy[j], cy);
            float dz = __fsub_rn(sz[j], cz);
            float d2 = __fadd_rn(__fadd_rn(__fmul_rn(dx,dx), __fmul_rn(dy,dy)),
                                 __fmul_rn(dz,dz));
            bool hit = (d2 <= R2);
            unsigned mask = __ballot_sync(0xffffffffu, hit);
            if (hit) {
                int pos = cnt + __popc(mask & lmask);
                if (pos < 32) f[pos] = j;
            }
            cnt += __popc(mask);
            if (cnt >= 32) break;
        }
        __syncwarp();
        int j = (lane < cnt) ? f[lane] : f[0];
        __syncwarp();

        float fx = sx[j]-cx, fy = sy[j]-cy, fz = sz[j]-cz;
        float p0 = points[(b*3+0)*NN + j];
        float p1 = points[(b*3+1)*NN + j];
        float p2 = points[(b*3+2)*NN + j];

        size_t base = ((size_t)(b*SS + s)*NSAMP + lane) * 8;
        *(float4*)(g_feat + base)     = make_float4(fx, fy, fz, p0);
        *(float4*)(g_feat + base + 4) = make_float4(p1, p2, 0.f, 0.f);

        float fv[6] = {fx, fy, fz, p0, p1, p2};
        int k = 0;
        #pragma unroll
        for (int c = 0; c < 6; c++) {
            s1[c] += fv[c];
            #pragma unroll
            for (int c2 = 0; c2 <= c; c2++) s2[k++] += fv[c]*fv[c2];
        }
    }

    __shared__ float red[27];
    if (tid < 27) red[tid] = 0.f;
    __syncthreads();
    #pragma unroll
    for (int i = 0; i < 6; i++) {
        float v = s1[i];
        for (int off = 16; off; off >>= 1) v += __shfl_down_sync(0xffffffffu, v, off);
        if (lane == 0) atomicAdd(&red[i], v);
    }
    #pragma unroll
    for (int i = 0; i < 21; i++) {
        float v = s2[i];
        for (int off = 16; off; off >>= 1) v += __shfl_down_sync(0xffffffffu, v, off);
        if (lane == 0) atomicAdd(&red[6+i], v);
    }
    __syncthreads();
    if (tid < 6)       atomicAdd(&g_fsum[tid], red[tid]);
    else if (tid < 27) atomicAdd(&g_fmom[tid-6], red[tid]);
}

// ---------------- BN1 fold helper (per-block, into smem) ----------------
static __device__ __forceinline__ void bn1_fold_block(
        const float* __restrict__ W1, const float* __restrict__ g1,
        const float* __restrict__ b1, float* sW1, float* sB1,
        float* sMu /*6*/, float* sC /*36*/, int t) {
    if (t == 0) {
        const float inv = 1.0f / (float)NSAMPLES;
        for (int c = 0; c < 6; c++) sMu[c] = g_fsum[c]*inv;
        int k = 0;
        for (int c = 0; c < 6; c++)
            for (int c2 = 0; c2 <= c; c2++) {
                float v = g_fmom[k++]*inv; sC[c*6+c2] = v; sC[c2*6+c] = v;
            }
    }
    __syncthreads();
    if (t < 64) {
        float w[6];
        #pragma unroll
        for (int c = 0; c < 6; c++) w[c] = W1[t*6+c];
        float mean = 0.f;
        #pragma unroll
        for (int c = 0; c < 6; c++) mean += w[c]*sMu[c];
        float e2 = 0.f;
        #pragma unroll
        for (int c = 0; c < 6; c++) {
            float tt = 0.f;
            #pragma unroll
            for (int c2 = 0; c2 < 6; c2++) tt += sC[c*6+c2]*w[c2];
            e2 += w[c]*tt;
        }
        float var = fmaxf(e2 - mean*mean, 0.f);
        float sc = g1[t]*rsqrtf(var + BNEPS);
        #pragma unroll
        for (int c = 0; c < 6; c++) sW1[t*6+c] = w[c]*sc;
        sB1[t] = b1[t] - mean*sc;
    }
    __syncthreads();
}

// ---------------- K2: stats — h1 mean + SYRK, feat prefetch pipelined --------
#define P1PAD 134
__global__ __launch_bounds__(256) void k_stats(const float* __restrict__ W1,
                                               const float* __restrict__ g1,
                                               const float* __restrict__ b1) {
    extern __shared__ float sm[];
    float* sW1  = sm;              // 384
    float* sB1  = sm + 384;        // 64
    float* ssum = sm + 448;        // 64
    float* sMu  = sm + 512;        // 6
    float* sC   = sm + 518;        // 36 (pad to 560)
    float* sH   = sm + 560;        // 64*134 = 8576

    int t = threadIdx.x;
    if (t < 64) ssum[t] = 0.f;
    bn1_fold_block(W1, g1, b1, sW1, sB1, sMu, sC, t);

    int to = t & 15, ts = t >> 4;
    int sA = t & 127, kb = t >> 7;
    ull accM[16];
    #pragma unroll
    for (int i = 0; i < 16; i++) accM[i] = 0ull;

    const ull* ra[4]; const ull* rb[4];
    #pragma unroll
    for (int i = 0; i < 4; i++) ra[i] = (const ull*)&sH[(ts + 16*i)*P1PAD];
    #pragma unroll
    for (int j = 0; j < 4; j++) rb[j] = (const ull*)&sH[(to + 16*j)*P1PAD];

    // prefetch first tile's feat
    float4 f0, f1;
    {
        const float* fp = g_feat + ((size_t)blockIdx.x*128 + sA)*8;
        f0 = *(const float4*)fp;
        f1 = *(const float4*)(fp + 4);
    }

    for (int tile = blockIdx.x; tile < NTILES; tile += gridDim.x) {
        // step A: h1 tile from prefetched regs, layout [k][s]
        {
            float f[6] = {f0.x, f0.y, f0.z, f0.w, f1.x, f1.y};
            #pragma unroll 8
            for (int kk = 0; kk < 32; kk++) {
                int k = kb*32 + kk;
                float a = sB1[k];
                #pragma unroll
                for (int c = 0; c < 6; c++) a += f[c]*sW1[k*6+c];
                sH[k*P1PAD + sA] = fmaxf(a, 0.f);
            }
        }
        __syncthreads();
        // prefetch next tile's feat (in flight during sums + SYRK)
        int ntile = tile + gridDim.x;
        if (ntile < NTILES) {
            const float* fp = g_feat + ((size_t)ntile*128 + sA)*8;
            f0 = *(const float4*)fp;
            f1 = *(const float4*)(fp + 4);
        }
        // per-channel sums
        {
            int k = t & 63, q = t >> 6;
            float local = 0.f;
            #pragma unroll 8
            for (int m = 0; m < 32; m++) local += sH[k*P1PAD + q*32 + m];
            atomicAdd(&ssum[k], local);
        }
        // SYRK: M[a][b] += sum_s h[a][s]*h[b][s], a = ts+16i, b = to+16j
        #pragma unroll 2
        for (int s2 = 0; s2 < 64; s2++) {
            ull ha[4], hb[4];
            #pragma unroll
            for (int i = 0; i < 4; i++) ha[i] = ra[i][s2];
            #pragma unroll
            for (int j = 0; j < 4; j++) hb[j] = rb[j][s2];
            #pragma unroll
            for (int i = 0; i < 4; i++)
                #pragma unroll
                for (int j = 0; j < 4; j++) fma2(accM[i*4+j], ha[i], hb[j]);
        }
        __syncthreads();
    }

    #pragma unroll
    for (int i = 0; i < 4; i++)
        #pragma unroll
        for (int j = 0; j < 4; j++)
            atomicAdd(&g_M[(ts + 16*i)*64 + (to + 16*j)], hadd2(accM[i*4+j]));
    __syncthreads();
    if (t < 64) atomicAdd(&g_h1sum[t], ssum[t]);
}

// ---------------- K3: BN2 params (1024 thr) + BN1 fold ----------------------
#define BW 65
__global__ __launch_bounds__(1024) void k_bn2(const float* __restrict__ W1,
                      const float* __restrict__ g1, const float* __restrict__ b1,
                      const float* __restrict__ W2, const float* __restrict__ g2,
                      const float* __restrict__ b2) {
    __shared__ float sM[4096];
    __shared__ float sW[64*BW];      // W2 rows, pad 65 -> conflict-free column reads
    __shared__ float hm[64];
    __shared__ float partm[1024], partq[1024];
    __shared__ float sMu[6], sC[36];
    int t = threadIdx.x;  // 1024
    for (int i = t; i < 4096; i += 1024) {
        sM[i] = g_M[i];
        sW[(i >> 6)*BW + (i & 63)] = W2[i];
    }
    if (t < 64) hm[t] = g_h1sum[t] * (1.0f/(float)NSAMPLES);
    if (t == 0) {
        const float inv = 1.0f / (float)NSAMPLES;
        for (int c = 0; c < 6; c++) sMu[c] = g_fsum[c]*inv;
        int k = 0;
        for (int c = 0; c < 6; c++)
            for (int c2 = 0; c2 <= c; c2++) {
                float v = g_fmom[k++]*inv; sC[c*6+c2] = v; sC[c2*6+c] = v;
            }
    }
    __syncthreads();
    // BN1 fold -> globals for k_fused
    if (t < 64) {
        float w[6];
        #pragma unroll
        for (int c = 0; c < 6; c++) w[c] = W1[t*6+c];
        float mean = 0.f;
        #pragma unroll
        for (int c = 0; c < 6; c++) mean += w[c]*sMu[c];
        float e2 = 0.f;
        #pragma unroll
        for (int c = 0; c < 6; c++) {
            float tt = 0.f;
            #pragma unroll
            for (int c2 = 0; c2 < 6; c2++) tt += sC[c*6+c2]*w[c2];
            e2 += w[c]*tt;
        }
        float var = fmaxf(e2 - mean*mean, 0.f);
        float sc = g1[t]*rsqrtf(var + BNEPS);
        #pragma unroll
        for (int c = 0; c < 6; c++) g_W1s[t*6+c] = w[c]*sc;
        g_b1s[t] = b1[t] - mean*sc;
    }
    // BN2: channel o handled by 16 threads (q = k-sixteenth, 4 k's each)
    int o = t & 63, q = t >> 6;
    const float* w = &sW[o*BW];
    float lm = 0.f, lq = 0.f;
    for (int k = q*4; k < q*4 + 4; k++) {
        float wk = w[k];
        lm += wk*hm[k];
        float s = 0.f;
        #pragma unroll 8
        for (int k2 = 0; k2 < 64; k2++) s += sM[k*64 + k2]*w[k2];
        lq += wk*s;
    }
    partm[t] = lm; partq[t] = lq;
    __syncthreads();
    if (t < 64) {
        float m = 0.f, qv = 0.f;
        #pragma unroll
        for (int i = 0; i < 16; i++) { m += partm[t + 64*i]; qv += partq[t + 64*i]; }
        qv *= (1.0f/(float)NSAMPLES);
        float var = fmaxf(qv - m*m, 0.f);
        float sc = g2[t]*rsqrtf(var + BNEPS);
        g_sc2[t] = sc; g_sh2[t] = b2[t] - m*sc;
    }
}

// ---------------- K4: fused feat->h1->x2->bn2/relu->x3 ------------------------
// GEMM1: 4x8 tiles; GEMM2: single-pass 8x8 (h read once, 1.0 B/MAC).
// occ 1 (reg-heavy); g_feat prefetched into regs first so LDG latency hides
// under the weight-staging phase.
#define WPAD 66
#define HPAD 70
__global__ __launch_bounds__(256, 1) void k_fused(const float* __restrict__ W2,
                                                  const float* __restrict__ W3) {
    extern __shared__ float sm[];
    float* sW1  = sm;                  // 384
    float* sB1  = sm + 384;            // 64
    float* sc2s = sm + 448;            // 64
    float* sh2s = sm + 512;            // 64
    float* csum = sm + 576;            // 128
    float* csq  = sm + 704;            // 128
    float* sW2  = sm + 832;            // 64*66  = 4224
    float* sW3  = sm + 5056;           // 128*66 = 8448
    float* sH   = sm + 13504;          // 128*70 = 8960
    float* rmax = sm + 832;            // reuse sW2 after GEMM1: [16][128]
    float* rmin = sm + 832 + 2048;

    int t = threadIdx.x;
    size_t s0 = (size_t)blockIdx.x * 128;

    // prefetch this block's feat FIRST (overlaps weight staging below)
    int sA = t & 127, kb = t >> 7;
    float4 f0, f1;
    {
        const float* fp = g_feat + (s0 + sA)*8;
        f0 = *(const float4*)fp;
        f1 = *(const float4*)(fp + 4);
    }

    for (int i = t; i < 384; i += 256) sW1[i] = g_W1s[i];
    if (t < 64) { sB1[t] = g_b1s[t]; sc2s[t] = g_sc2[t]; sh2s[t] = g_sh2[t]; }
    if (t < 128){ csum[t] = 0.f; csq[t] = 0.f; }
    for (int i = t; i < 4096; i += 256) { int o = i >> 6, k = i & 63; sW2[o*WPAD + k] = W2[i]; }
    for (int i = t; i < 8192; i += 256) { int o = i >> 6, k = i & 63; sW3[o*WPAD + k] = W3[i]; }
    __syncthreads();

    // step A: h1 into sH[s][k] (float2 stores: 8B-aligned for all s)
    {
        float f[6] = {f0.x, f0.y, f0.z, f0.w, f1.x, f1.y};
        float* dst = &sH[sA*HPAD + kb*32];
        #pragma unroll 4
        for (int m = 0; m < 16; m++) {
            float2 hv;
            #pragma unroll
            for (int q = 0; q < 2; q++) {
                int k = kb*32 + m*2 + q;
                float a = sB1[k];
                #pragma unroll
                for (int c = 0; c < 6; c++) a += f[c]*sW1[k*6+c];
                (&hv.x)[q] = fmaxf(a, 0.f);
            }
            *(float2*)(dst + m*2) = hv;
        }
    }
    __syncthreads();

    int to = t & 15, ts = t >> 4;
    const ull* hrow[8];
    #pragma unroll
    for (int j = 0; j < 8; j++) hrow[j] = (const ull*)&sH[(ts*8 + j)*HPAD];

    // GEMM1: x2[o][s], o = to + 16i (i<4), s = ts*8+j
    float h2v[4][8];
    {
        ull acc[32];
        #pragma unroll
        for (int i = 0; i < 32; i++) acc[i] = 0ull;
        const ull* wrow[4];
        #pragma unroll
        for (int i = 0; i < 4; i++) wrow[i] = (const ull*)&sW2[(to + 16*i)*WPAD];
        #pragma unroll 2
        for (int k2 = 0; k2 < 32; k2++) {
            ull wv[4], hv[8];
            #pragma unroll
            for (int i = 0; i < 4; i++) wv[i] = wrow[i][k2];
            #pragma unroll
            for (int j = 0; j < 8; j++) hv[j] = hrow[j][k2];
            #pragma unroll
            for (int i = 0; i < 4; i++)
                #pragma unroll
                for (int j = 0; j < 8; j++) fma2(acc[i*8+j], wv[i], hv[j]);
        }
        #pragma unroll
        for (int i = 0; i < 4; i++) {
            int o = to + 16*i;
            float sc = sc2s[o], sh = sh2s[o];
            #pragma unroll
            for (int j = 0; j < 8; j++)
                h2v[i][j] = fmaxf(hadd2(acc[i*8+j])*sc + sh, 0.f);
        }
    }
    __syncthreads();   // all GEMM1 reads of sH done (sW2 also free now)

    // write h2 into sH[s][k]
    #pragma unroll
    for (int i = 0; i < 4; i++) {
        int o = to + 16*i;
        #pragma unroll
        for (int j = 0; j < 8; j++) sH[(ts*8 + j)*HPAD + o] = h2v[i][j];
    }
    __syncthreads();

    // GEMM2: x3[o][s], o = to + 16i (i<8) — single pass, h read once
    {
        ull acc[64];
        #pragma unroll
        for (int i = 0; i < 64; i++) acc[i] = 0ull;
        const ull* wrow[8];
        #pragma unroll
        for (int i = 0; i < 8; i++) wrow[i] = (const ull*)&sW3[(to + 16*i)*WPAD];
        #pragma unroll 2
        for (int k2 = 0; k2 < 32; k2++) {
            ull wv[8], hv[8];
            #pragma unroll
            for (int i = 0; i < 8; i++) wv[i] = wrow[i][k2];
            #pragma unroll
            for (int j = 0; j < 8; j++) hv[j] = hrow[j][k2];
            #pragma unroll
            for (int i = 0; i < 8; i++)
                #pragma unroll
                for (int j = 0; j < 8; j++) fma2(acc[i*8+j], wv[i], hv[j]);
        }
        #pragma unroll
        for (int i = 0; i < 8; i++) {
            int o = to + 16*i;
            float ps = 0.f, pq = 0.f, mx = -INFINITY, mn = INFINITY;
            #pragma unroll
            for (int j = 0; j < 8; j++) {
                float x = hadd2(acc[i*8+j]);
                ps += x; pq += x*x; mx = fmaxf(mx, x); mn = fminf(mn, x);
            }
            atomicAdd(&csum[o], ps);
            atomicAdd(&csq[o], pq);
            rmax[ts*128 + o] = mx;
            rmin[ts*128 + o] = mn;
        }
    }
    __syncthreads();

    // reduce 4 ts-rows per group (group = 32 samples)
    for (int v = t; v < 512; v += 256) {
        int gq = v >> 7, o = v & 127;
        float mx = rmax[(gq*4+0)*128 + o];
        mx = fmaxf(mx, rmax[(gq*4+1)*128 + o]);
        mx = fmaxf(mx, rmax[(gq*4+2)*128 + o]);
        mx = fmaxf(mx, rmax[(gq*4+3)*128 + o]);
        float mn = rmin[(gq*4+0)*128 + o];
        mn = fminf(mn, rmin[(gq*4+1)*128 + o]);
        mn = fminf(mn, rmin[(gq*4+2)*128 + o]);
        mn = fminf(mn, rmin[(gq*4+3)*128 + o]);
        size_t g = s0/32 + gq;
        g_gmax[g*128 + o] = mx;
        g_gmin[g*128 + o] = mn;
    }
    __syncthreads();
    if (t < 128) { atomicAdd(&g_x3sum[t], csum[t]); atomicAdd(&g_x3sq[t], csq[t]); }
}

// ---------------- K5: bn3 (inline) + relu on group max/min, transposed out ----
__global__ void k_out2(const float* __restrict__ g3, const float* __restrict__ b3,
                       float* __restrict__ out2) {
    __shared__ float tr[32*129];
    __shared__ float ssc[128], ssh[128];
    int b = blockIdx.y;
    int s0 = blockIdx.x * 32;
    int t = threadIdx.x;
    if (t < 128) {
        const float inv = 1.0f / (float)NSAMPLES;
        float m = g_x3sum[t]*inv;
        float v = fmaxf(g_x3sq[t]*inv - m*m, 0.f);
        float sc = g3[t]*rsqrtf(v + BNEPS);
        ssc[t] = sc; ssh[t] = b3[t] - m*sc;
    }
    __syncthreads();
    for (int i = t; i < 32*128; i += 256) {
        int gi = i >> 7, o = i & 127;
        float sc = ssc[o], sh = ssh[o];
        size_t g = (size_t)(b*SS + s0 + gi);
        float v = (sc >= 0.f) ? g_gmax[g*128 + o] : g_gmin[g*128 + o];
        tr[gi*129 + o] = fmaxf(sc*v + sh, 0.f);
    }
    __syncthreads();
    for (int i = t; i < 32*128; i += 256) {
        int o = i >> 5, si = i & 31;
        out2[((size_t)(b*128 + o))*SS + s0 + si] = tr[si*129 + o];
    }
}

// ---------------- launch ----------------
extern "C" void kernel_launch(void* const* d_in, const int* in_sizes, int n_in,
                              void* d_out, int out_size) {
    const float* xyz    = (const float*)d_in[0];
    const float* points = (const float*)d_in[1];
    const int*   fps    = (const int*)  d_in[2];
    const float* W1 = (const float*)d_in[3];
    const float* g1 = (const float*)d_in[4];
    const float* b1 = (const float*)d_in[5];
    const float* W2 = (const float*)d_in[6];
    const float* g2 = (const float*)d_in[7];
    const float* b2 = (const float*)d_in[8];
    const float* W3 = (const float*)d_in[9];
    const float* g3 = (const float*)d_in[10];
    const float* b3 = (const float*)d_in[11];

    float* out1 = (float*)d_out;
    float* out2 = (float*)d_out + (size_t)BB*3*SS;

    const int SMEM_BALL  = (3*NN)*4 + 8*32*4;                    // 99328
    const int SMEM_STATS = (560 + 64*P1PAD)*4;                   // 36544
    const int SMEM_FUSED = (13504 + 128*HPAD)*4;                 // 89856

    cudaFuncSetAttribute(k_ball,  cudaFuncAttributeMaxDynamicSharedMemorySize, SMEM_BALL);
    cudaFuncSetAttribute(k_stats, cudaFuncAttributeMaxDynamicSharedMemorySize, SMEM_STATS);
    cudaFuncSetAttribute(k_fused, cudaFuncAttributeMaxDynamicSharedMemorySize, SMEM_FUSED);

    k_zero<<<1, 256>>>();
    k_ball<<<dim3(SS/32, BB), 256, SMEM_BALL>>>(xyz, points, fps, out1);
    k_stats<<<592, 256, SMEM_STATS>>>(W1, g1, b1);
    k_bn2<<<1, 1024>>>(W1, g1, b1, W2, g2, b2);
    k_fused<<<NTILES, 256, SMEM_FUSED>>>(W2, W3);
    k_out2<<<dim3(SS/32, BB), 256>>>(g3, b3, out2);
}

// round 7
// speedup vs baseline: 1.0365x; 1.0365x over previous
#include <cuda_runtime.h>
#include <math.h>
#include <stdint.h>

#define BB 8
#define NN 8192
#define SS 2048
#define NSAMP 32
#define NSAMPLES (BB*SS*NSAMP)   /* 524288 */
#define NGROUPS (BB*SS)          /* 16384  */
#define NTILES (NSAMPLES/128)    /* 4096   */
#define R2 0.04f
#define BNEPS 1e-5f

typedef unsigned long long ull;

// ---------------- device scratch ----------------
__device__ float g_feat[(size_t)NSAMPLES*8];     // [sample][8] (6 used)
__device__ float g_gmax[(size_t)NGROUPS*128];
__device__ float g_gmin[(size_t)NGROUPS*128];
__device__ float g_fsum[6];
__device__ float g_fmom[21];
__device__ float g_M[64*64];                     // canonical-half of sum h1 h1^T
__device__ float g_h1sum[64];
__device__ float g_x3sum[128], g_x3sq[128];
__device__ float g_W1s[64*6], g_b1s[64];         // BN1 folded into W1 (written by k_bn2)
__device__ float g_sc2[64], g_sh2[64];

// ---------------- f32x2 helpers ----------------
static __device__ __forceinline__ void fma2(ull& d, ull a, ull b) {
    asm("fma.rn.f32x2 %0, %1, %2, %0;" : "+l"(d) : "l"(a), "l"(b));
}
static __device__ __forceinline__ float hadd2(ull v) {
    float lo, hi;
    asm("mov.b64 {%0,%1}, %2;" : "=f"(lo), "=f"(hi) : "l"(v));
    return lo + hi;
}

// ---------------- K0: zero accumulators ----------------
__global__ void k_zero() {
    int t = threadIdx.x;
    for (int i = t; i < 4096; i += 256) g_M[i] = 0.f;
    if (t < 6)  g_fsum[t] = 0.f;
    if (t < 21) g_fmom[t] = 0.f;
    if (t < 64) g_h1sum[t] = 0.f;
    if (t < 128){ g_x3sum[t] = 0.f; g_x3sq[t] = 0.f; }
}

// ---------------- K1: ball query + feat + feat moments + out1 ----------------
__global__ __launch_bounds__(256) void k_ball(const float* __restrict__ xyz,
                                              const float* __restrict__ points,
                                              const int*   __restrict__ fps,
                                              float* __restrict__ out1) {
    extern __shared__ float sm[];
    float* sx = sm;
    float* sy = sm + NN;
    float* sz = sm + 2*NN;
    int*   fnd = (int*)(sm + 3*NN);   // [8 warps][32]

    int b = blockIdx.y;
    int qbase = blockIdx.x * 32;
    int tid = threadIdx.x;

    for (int i = tid; i < NN; i += 256) {
        sx[i] = xyz[(b*3+0)*NN + i];
        sy[i] = xyz[(b*3+1)*NN + i];
        sz[i] = xyz[(b*3+2)*NN + i];
    }
    __syncthreads();

    int w = tid >> 5, lane = tid & 31;
    int* f = fnd + w*32;
    unsigned lmask = (1u << lane) - 1u;

    float s1[6], s2[21];
    #pragma unroll
    for (int i = 0; i < 6; i++)  s1[i] = 0.f;
    #pragma unroll
    for (int i = 0; i < 21; i++) s2[i] = 0.f;

    for (int qi = 0; qi < 4; qi++) {
        int s = qbase + w*4 + qi;
        int cidx = fps[b*SS + s];
        float cx = sx[cidx], cy = sy[cidx], cz = sz[cidx];
        if (lane == 0) {
            out1[(b*3+0)*SS + s] = cx;
            out1[(b*3+1)*SS + s] = cy;
            out1[(b*3+2)*SS + s] = cz;
        }
        int cnt = 0;
        for (int chunk = 0; chunk < NN/32; chunk++) {
            int j = chunk*32 + lane;
            float dx = __fsub_rn(sx[j], cx);
            float dy = __fsub_rn(sy[j], cy);
            float dz = __fsub_rn(sz[j], cz);
            float d2 = __fadd_rn(__fadd_rn(__fmul_rn(dx,dx), __fmul_rn(dy,dy)),
                                 __fmul_rn(dz,dz));
            bool hit = (d2 <= R2);
            unsigned mask = __ballot_sync(0xffffffffu, hit);
            if (hit) {
                int pos = cnt + __popc(mask & lmask);
                if (pos < 32) f[pos] = j;
            }
            cnt += __popc(mask);
            if (cnt >= 32) break;
        }
        __syncwarp();
        int j = (lane < cnt) ? f[lane] : f[0];
        __syncwarp();

        float fx = sx[j]-cx, fy = sy[j]-cy, fz = sz[j]-cz;
        float p0 = points[(b*3+0)*NN + j];
        float p1 = points[(b*3+1)*NN + j];
        float p2 = points[(b*3+2)*NN + j];

        size_t base = ((size_t)(b*SS + s)*NSAMP + lane) * 8;
        *(float4*)(g_feat + base)     = make_float4(fx, fy, fz, p0);
        *(float4*)(g_feat + base + 4) = make_float4(p1, p2, 0.f, 0.f);

        float fv[6] = {fx, fy, fz, p0, p1, p2};
        int k = 0;
        #pragma unroll
        for (int c = 0; c < 6; c++) {
            s1[c] += fv[c];
            #pragma unroll
            for (int c2 = 0; c2 <= c; c2++) s2[k++] += fv[c]*fv[c2];
        }
    }

    __shared__ float red[27];
    if (tid < 27) red[tid] = 0.f;
    __syncthreads();
    #pragma unroll
    for (int i = 0; i < 6; i++) {
        float v = s1[i];
        for (int off = 16; off; off >>= 1) v += __shfl_down_sync(0xffffffffu, v, off);
        if (lane == 0) atomicAdd(&red[i], v);
    }
    #pragma unroll
    for (int i = 0; i < 21; i++) {
        float v = s2[i];
        for (int off = 16; off; off >>= 1) v += __shfl_down_sync(0xffffffffu, v, off);
        if (lane == 0) atomicAdd(&red[6+i], v);
    }
    __syncthreads();
    if (tid < 6)       atomicAdd(&g_fsum[tid], red[tid]);
    else if (tid < 27) atomicAdd(&g_fmom[tid-6], red[tid]);
}

// ---------------- BN1 fold helper (per-block, into smem) ----------------
static __device__ __forceinline__ void bn1_fold_block(
        const float* __restrict__ W1, const float* __restrict__ g1,
        const float* __restrict__ b1, float* sW1, float* sB1,
        float* sMu /*6*/, float* sC /*36*/, int t) {
    if (t == 0) {
        const float inv = 1.0f / (float)NSAMPLES;
        for (int c = 0; c < 6; c++) sMu[c] = g_fsum[c]*inv;
        int k = 0;
        for (int c = 0; c < 6; c++)
            for (int c2 = 0; c2 <= c; c2++) {
                float v = g_fmom[k++]*inv; sC[c*6+c2] = v; sC[c2*6+c] = v;
            }
    }
    __syncthreads();
    if (t < 64) {
        float w[6];
        #pragma unroll
        for (int c = 0; c < 6; c++) w[c] = W1[t*6+c];
        float mean = 0.f;
        #pragma unroll
        for (int c = 0; c < 6; c++) mean += w[c]*sMu[c];
        float e2 = 0.f;
        #pragma unroll
        for (int c = 0; c < 6; c++) {
            float tt = 0.f;
            #pragma unroll
            for (int c2 = 0; c2 < 6; c2++) tt += sC[c*6+c2]*w[c2];
            e2 += w[c]*tt;
        }
        float var = fmaxf(e2 - mean*mean, 0.f);
        float sc = g1[t]*rsqrtf(var + BNEPS);
        #pragma unroll
        for (int c = 0; c < 6; c++) sW1[t*6+c] = w[c]*sc;
        sB1[t] = b1[t] - mean*sc;
    }
    __syncthreads();
}

// ---------------- K2: stats — h1 mean + SYMMETRIC SYRK ----------------------
// Thread (ts,to) computes canonical block (u,v)=(min,max):
//   ts<to: samples 0-63; ts>to: samples 64-127; ts==to: all 128.
// Inactive lanes issue no smem wavefronts -> SYRK LDS traffic ~halved.
#define P1PAD 134
__global__ __launch_bounds__(256) void k_stats(const float* __restrict__ W1,
                                               const float* __restrict__ g1,
                                               const float* __restrict__ b1) {
    extern __shared__ float sm[];
    float* sW1  = sm;              // 384
    float* sB1  = sm + 384;        // 64
    float* ssum = sm + 448;        // 64
    float* sMu  = sm + 512;        // 6
    float* sC   = sm + 518;        // 36 (pad to 560)
    float* sH   = sm + 560;        // 64*134 = 8576

    int t = threadIdx.x;
    if (t < 64) ssum[t] = 0.f;
    bn1_fold_block(W1, g1, b1, sW1, sB1, sMu, sC, t);

    int to = t & 15, ts = t >> 4;
    int u = (ts < to) ? ts : to;
    int v = (ts < to) ? to : ts;
    int sBeg = (ts > to) ? 32 : 0;
    int sEnd = (ts < to) ? 32 : 64;

    ull accM[16];
    #pragma unroll
    for (int i = 0; i < 16; i++) accM[i] = 0ull;

    const ull* ra[4]; const ull* rb[4];
    #pragma unroll
    for (int i = 0; i < 4; i++) ra[i] = (const ull*)&sH[(u + 16*i)*P1PAD];
    #pragma unroll
    for (int j = 0; j < 4; j++) rb[j] = (const ull*)&sH[(v + 16*j)*P1PAD];

    for (int tile = blockIdx.x; tile < NTILES; tile += gridDim.x) {
        size_t s0 = (size_t)tile * 128;
        // h1 tile: sample s, 32 channels per thread, layout [k][s]
        {
            int s = t & 127, kb = t >> 7;
            const float* fp = g_feat + (s0 + s)*8;
            float4 f0 = *(const float4*)fp;
            float4 f1 = *(const float4*)(fp + 4);
            float f[6] = {f0.x, f0.y, f0.z, f0.w, f1.x, f1.y};
            #pragma unroll 8
            for (int kk = 0; kk < 32; kk++) {
                int k = kb*32 + kk;
                float a = sB1[k];
                #pragma unroll
                for (int c = 0; c < 6; c++) a += f[c]*sW1[k*6+c];
                sH[k*P1PAD + s] = fmaxf(a, 0.f);
            }
        }
        __syncthreads();
        // per-channel sums
        {
            int k = t & 63, q = t >> 6;
            float local = 0.f;
            #pragma unroll 8
            for (int m = 0; m < 32; m++) local += sH[k*P1PAD + q*32 + m];
            atomicAdd(&ssum[k], local);
        }
        // SYRK (canonical half)
        #pragma unroll 2
        for (int s2 = sBeg; s2 < sEnd; s2++) {
            ull ha[4], hb[4];
            #pragma unroll
            for (int i = 0; i < 4; i++) ha[i] = ra[i][s2];
            #pragma unroll
            for (int j = 0; j < 4; j++) hb[j] = rb[j][s2];
            #pragma unroll
            for (int i = 0; i < 4; i++)
                #pragma unroll
                for (int j = 0; j < 4; j++) fma2(accM[i*4+j], ha[i], hb[j]);
        }
        __syncthreads();
    }

    #pragma unroll
    for (int i = 0; i < 4; i++)
        #pragma unroll
        for (int j = 0; j < 4; j++)
            atomicAdd(&g_M[(u + 16*i)*64 + (v + 16*j)], hadd2(accM[i*4+j]));
    __syncthreads();
    if (t < 64) atomicAdd(&g_h1sum[t], ssum[t]);
}

// ---------------- K3: BN2 params (1024 thr, mirrored M load) + BN1 fold ------
#define BW 65
__global__ __launch_bounds__(1024) void k_bn2(const float* __restrict__ W1,
                      const float* __restrict__ g1, const float* __restrict__ b1,
                      const float* __restrict__ W2, const float* __restrict__ g2,
                      const float* __restrict__ b2) {
    __shared__ float sM[4096];
    __shared__ float sW[64*BW];      // W2 rows, pad 65 -> conflict-free column reads
    __shared__ float hm[64];
    __shared__ float partm[1024], partq[1024];
    __shared__ float sMu[6], sC[36];
    int t = threadIdx.x;  // 1024
    for (int i = t; i < 4096; i += 1024) {
        int r = i >> 6, c = i & 63;
        int src = ((r & 15) <= (c & 15)) ? i : c*64 + r;   // mirror canonical half
        sM[i] = g_M[src];
        sW[r*BW + c] = W2[i];
    }
    if (t < 64) hm[t] = g_h1sum[t] * (1.0f/(float)NSAMPLES);
    if (t == 0) {
        const float inv = 1.0f / (float)NSAMPLES;
        for (int c = 0; c < 6; c++) sMu[c] = g_fsum[c]*inv;
        int k = 0;
        for (int c = 0; c < 6; c++)
            for (int c2 = 0; c2 <= c; c2++) {
                float v = g_fmom[k++]*inv; sC[c*6+c2] = v; sC[c2*6+c] = v;
            }
    }
    __syncthreads();
    // BN1 fold -> globals for k_fused
    if (t < 64) {
        float w[6];
        #pragma unroll
        for (int c = 0; c < 6; c++) w[c] = W1[t*6+c];
        float mean = 0.f;
        #pragma unroll
        for (int c = 0; c < 6; c++) mean += w[c]*sMu[c];
        float e2 = 0.f;
        #pragma unroll
        for (int c = 0; c < 6; c++) {
            float tt = 0.f;
            #pragma unroll
            for (int c2 = 0; c2 < 6; c2++) tt += sC[c*6+c2]*w[c2];
            e2 += w[c]*tt;
        }
        float var = fmaxf(e2 - mean*mean, 0.f);
        float sc = g1[t]*rsqrtf(var + BNEPS);
        #pragma unroll
        for (int c = 0; c < 6; c++) g_W1s[t*6+c] = w[c]*sc;
        g_b1s[t] = b1[t] - mean*sc;
    }
    // BN2: channel o handled by 16 threads (q = k-sixteenth, 4 k's each)
    int o = t & 63, q = t >> 6;
    const float* w = &sW[o*BW];
    float lm = 0.f, lq = 0.f;
    for (int k = q*4; k < q*4 + 4; k++) {
        float wk = w[k];
        lm += wk*hm[k];
        float s = 0.f;
        #pragma unroll 8
        for (int k2 = 0; k2 < 64; k2++) s += sM[k*64 + k2]*w[k2];
        lq += wk*s;
    }
    partm[t] = lm; partq[t] = lq;
    __syncthreads();
    if (t < 64) {
        float m = 0.f, qv = 0.f;
        #pragma unroll
        for (int i = 0; i < 16; i++) { m += partm[t + 64*i]; qv += partq[t + 64*i]; }
        qv *= (1.0f/(float)NSAMPLES);
        float var = fmaxf(qv - m*m, 0.f);
        float sc = g2[t]*rsqrtf(var + BNEPS);
        g_sc2[t] = sc; g_sh2[t] = b2[t] - m*sc;
    }
}

// ---------------- K4: fused feat->h1->x2->bn2/relu->x3 (R5-proven, occ 2) ----
#define WPAD 66
#define HPAD 70
__global__ __launch_bounds__(256, 2) void k_fused(const float* __restrict__ W2,
                                                  const float* __restrict__ W3) {
    extern __shared__ float sm[];
    float* sW1  = sm;                  // 384
    float* sB1  = sm + 384;            // 64
    float* sc2s = sm + 448;            // 64
    float* sh2s = sm + 512;            // 64
    float* csum = sm + 576;            // 128
    float* csq  = sm + 704;            // 128
    float* sW2  = sm + 832;            // 64*66  = 4224
    float* sW3  = sm + 5056;           // 128*66 = 8448
    float* sH   = sm + 13504;          // 128*70 = 8960
    float* rmax = sm + 832;            // reuse sW2 after GEMM1: [16][128]
    float* rmin = sm + 832 + 2048;

    int t = threadIdx.x;
    for (int i = t; i < 384; i += 256) sW1[i] = g_W1s[i];
    if (t < 64) { sB1[t] = g_b1s[t]; sc2s[t] = g_sc2[t]; sh2s[t] = g_sh2[t]; }
    if (t < 128){ csum[t] = 0.f; csq[t] = 0.f; }
    for (int i = t; i < 4096; i += 256) { int o = i >> 6, k = i & 63; sW2[o*WPAD + k] = W2[i]; }
    for (int i = t; i < 8192; i += 256) { int o = i >> 6, k = i & 63; sW3[o*WPAD + k] = W3[i]; }
    __syncthreads();

    size_t s0 = (size_t)blockIdx.x * 128;

    // step A: h1 into sH[s][k] (float2 stores: 8B-aligned for all s)
    {
        int s = t & 127, kb = t >> 7;
        const float* fp = g_feat + (s0 + s)*8;
        float4 f0 = *(const float4*)fp;
        float4 f1 = *(const float4*)(fp + 4);
        float f[6] = {f0.x, f0.y, f0.z, f0.w, f1.x, f1.y};
        float* dst = &sH[s*HPAD + kb*32];
        #pragma unroll 4
        for (int m = 0; m < 16; m++) {
            float2 hv;
            #pragma unroll
            for (int q = 0; q < 2; q++) {
                int k = kb*32 + m*2 + q;
                float a = sB1[k];
                #pragma unroll
                for (int c = 0; c < 6; c++) a += f[c]*sW1[k*6+c];
                (&hv.x)[q] = fmaxf(a, 0.f);
            }
            *(float2*)(dst + m*2) = hv;
        }
    }
    __syncthreads();

    int to = t & 15, ts = t >> 4;
    const ull* hrow[8];
    #pragma unroll
    for (int j = 0; j < 8; j++) hrow[j] = (const ull*)&sH[(ts*8 + j)*HPAD];

    // GEMM1: x2[o][s], o = to + 16i (i<4), s = ts*8+j
    float h2v[4][8];
    {
        ull acc[32];
        #pragma unroll
        for (int i = 0; i < 32; i++) acc[i] = 0ull;
        const ull* wrow[4];
        #pragma unroll
        for (int i = 0; i < 4; i++) wrow[i] = (const ull*)&sW2[(to + 16*i)*WPAD];
        #pragma unroll 2
        for (int k2 = 0; k2 < 32; k2++) {
            ull wv[4], hv[8];
            #pragma unroll
            for (int i = 0; i < 4; i++) wv[i] = wrow[i][k2];
            #pragma unroll
            for (int j = 0; j < 8; j++) hv[j] = hrow[j][k2];
            #pragma unroll
            for (int i = 0; i < 4; i++)
                #pragma unroll
                for (int j = 0; j < 8; j++) fma2(acc[i*8+j], wv[i], hv[j]);
        }
        #pragma unroll
        for (int i = 0; i < 4; i++) {
            int o = to + 16*i;
            float sc = sc2s[o], sh = sh2s[o];
            #pragma unroll
            for (int j = 0; j < 8; j++)
                h2v[i][j] = fmaxf(hadd2(acc[i*8+j])*sc + sh, 0.f);
        }
    }
    __syncthreads();   // all GEMM1 reads of sH done (sW2 also free now)

    // write h2 into sH[s][k]
    #pragma unroll
    for (int i = 0; i < 4; i++) {
        int o = to + 16*i;
        #pragma unroll
        for (int j = 0; j < 8; j++) sH[(ts*8 + j)*HPAD + o] = h2v[i][j];
    }
    __syncthreads();

    // GEMM2: x3[o][s] in two o-halves; o = half*64 + to + 16i
    for (int half = 0; half < 2; half++) {
        ull acc[32];
        #pragma unroll
        for (int i = 0; i < 32; i++) acc[i] = 0ull;
        const ull* wrow[4];
        #pragma unroll
        for (int i = 0; i < 4; i++) wrow[i] = (const ull*)&sW3[(half*64 + to + 16*i)*WPAD];
        #pragma unroll 2
        for (int k2 = 0; k2 < 32; k2++) {
            ull wv[4], hv[8];
            #pragma unroll
            for (int i = 0; i < 4; i++) wv[i] = wrow[i][k2];
            #pragma unroll
            for (int j = 0; j < 8; j++) hv[j] = hrow[j][k2];
            #pragma unroll
            for (int i = 0; i < 4; i++)
                #pragma unroll
                for (int j = 0; j < 8; j++) fma2(acc[i*8+j], wv[i], hv[j]);
        }
        #pragma unroll
        for (int i = 0; i < 4; i++) {
            int o = half*64 + to + 16*i;
            float ps = 0.f, pq = 0.f, mx = -INFINITY, mn = INFINITY;
            #pragma unroll
            for (int j = 0; j < 8; j++) {
                float x = hadd2(acc[i*8+j]);
                ps += x; pq += x*x; mx = fmaxf(mx, x); mn = fminf(mn, x);
            }
            atomicAdd(&csum[o], ps);
            atomicAdd(&csq[o], pq);
            rmax[ts*128 + o] = mx;
            rmin[ts*128 + o] = mn;
        }
    }
    __syncthreads();

    // reduce 4 ts-rows per group (group = 32 samples)
    for (int v = t; v < 512; v += 256) {
        int gq = v >> 7, o = v & 127;
        float mx = rmax[(gq*4+0)*128 + o];
        mx = fmaxf(mx, rmax[(gq*4+1)*128 + o]);
        mx = fmaxf(mx, rmax[(gq*4+2)*128 + o]);
        mx = fmaxf(mx, rmax[(gq*4+3)*128 + o]);
        float mn = rmin[(gq*4+0)*128 + o];
        mn = fminf(mn, rmin[(gq*4+1)*128 + o]);
        mn = fminf(mn, rmin[(gq*4+2)*128 + o]);
        mn = fminf(mn, rmin[(gq*4+3)*128 + o]);
        size_t g = s0/32 + gq;
        g_gmax[g*128 + o] = mx;
        g_gmin[g*128 + o] = mn;
    }
    __syncthreads();
    if (t < 128) { atomicAdd(&g_x3sum[t], csum[t]); atomicAdd(&g_x3sq[t], csq[t]); }
}

// ---------------- K5: bn3 (inline) + relu on group max/min, transposed out ----
__global__ void k_out2(const float* __restrict__ g3, const float* __restrict__ b3,
                       float* __restrict__ out2) {
    __shared__ float tr[32*129];
    __shared__ float ssc[128], ssh[128];
    int b = blockIdx.y;
    int s0 = blockIdx.x * 32;
    int t = threadIdx.x;
    if (t < 128) {
        const float inv = 1.0f / (float)NSAMPLES;
        float m = g_x3sum[t]*inv;
        float v = fmaxf(g_x3sq[t]*inv - m*m, 0.f);
        float sc = g3[t]*rsqrtf(v + BNEPS);
        ssc[t] = sc; ssh[t] = b3[t] - m*sc;
    }
    __syncthreads();
    for (int i = t; i < 32*128; i += 256) {
        int gi = i >> 7, o = i & 127;
        float sc = ssc[o], sh = ssh[o];
        size_t g = (size_t)(b*SS + s0 + gi);
        float v = (sc >= 0.f) ? g_gmax[g*128 + o] : g_gmin[g*128 + o];
        tr[gi*129 + o] = fmaxf(sc*v + sh, 0.f);
    }
    __syncthreads();
    for (int i = t; i < 32*128; i += 256) {
        int o = i >> 5, si = i & 31;
        out2[((size_t)(b*128 + o))*SS + s0 + si] = tr[si*129 + o];
    }
}

// ---------------- launch ----------------
extern "C" void kernel_launch(void* const* d_in, const int* in_sizes, int n_in,
                              void* d_out, int out_size) {
    const float* xyz    = (const float*)d_in[0];
    const float* points = (const float*)d_in[1];
    const int*   fps    = (const int*)  d_in[2];
    const float* W1 = (const float*)d_in[3];
    const float* g1 = (const float*)d_in[4];
    const float* b1 = (const float*)d_in[5];
    const float* W2 = (const float*)d_in[6];
    const float* g2 = (const float*)d_in[7];
    const float* b2 = (const float*)d_in[8];
    const float* W3 = (const float*)d_in[9];
    const float* g3 = (const float*)d_in[10];
    const float* b3 = (const float*)d_in[11];

    float* out1 = (float*)d_out;
    float* out2 = (float*)d_out + (size_t)BB*3*SS;

    const int SMEM_BALL  = (3*NN)*4 + 8*32*4;                    // 99328
    const int SMEM_STATS = (560 + 64*P1PAD)*4;                   // 36544
    const int SMEM_FUSED = (13504 + 128*HPAD)*4;                 // 89856

    cudaFuncSetAttribute(k_ball,  cudaFuncAttributeMaxDynamicSharedMemorySize, SMEM_BALL);
    cudaFuncSetAttribute(k_stats, cudaFuncAttributeMaxDynamicSharedMemorySize, SMEM_STATS);
    cudaFuncSetAttribute(k_fused, cudaFuncAttributeMaxDynamicSharedMemorySize, SMEM_FUSED);

    k_zero<<<1, 256>>>();
    k_ball<<<dim3(SS/32, BB), 256, SMEM_BALL>>>(xyz, points, fps, out1);
    k_stats<<<592, 256, SMEM_STATS>>>(W1, g1, b1);
    k_bn2<<<1, 1024>>>(W1, g1, b1, W2, g2, b2);
    k_fused<<<NTILES, 256, SMEM_FUSED>>>(W2, W3);
    k_out2<<<dim3(SS/32, BB), 256>>>(g3, b3, out2);
}

// round 8
// speedup vs baseline: 1.0949x; 1.0563x over previous
#include <cuda_runtime.h>
#include <math.h>
#include <stdint.h>

#define BB 8
#define NN 8192
#define SS 2048
#define NSAMP 32
#define NSAMPLES (BB*SS*NSAMP)   /* 524288 */
#define NGROUPS (BB*SS)          /* 16384  */
#define NTILES (NSAMPLES/128)    /* 4096   */
#define R2 0.04f
#define BNEPS 1e-5f

typedef unsigned long long ull;

// ---------------- device scratch ----------------
__device__ float g_feat[(size_t)NSAMPLES*8];     // [sample][8] (6 used)
__device__ float g_gmax[(size_t)NGROUPS*128];
__device__ float g_gmin[(size_t)NGROUPS*128];
__device__ float g_fsum[6];
__device__ float g_fmom[21];
__device__ float g_M[64*64];                     // sum over samples of h1 h1^T
__device__ float g_h1sum[64];
__device__ float g_x3sum[128], g_x3sq[128];
__device__ float g_W1s[64*6], g_b1s[64];         // BN1 folded into W1
__device__ float g_sc2[64], g_sh2[64];
__device__ unsigned g_cnt;                       // k_stats completion counter

// ---------------- f32x2 helpers ----------------
static __device__ __forceinline__ void fma2(ull& d, ull a, ull b) {
    asm("fma.rn.f32x2 %0, %1, %2, %0;" : "+l"(d) : "l"(a), "l"(b));
}
static __device__ __forceinline__ float hadd2(ull v) {
    float lo, hi;
    asm("mov.b64 {%0,%1}, %2;" : "=f"(lo), "=f"(hi) : "l"(v));
    return lo + hi;
}

// ---------------- K0: zero accumulators ----------------
__global__ void k_zero() {
    int t = threadIdx.x;
    for (int i = t; i < 4096; i += 256) g_M[i] = 0.f;
    if (t < 6)  g_fsum[t] = 0.f;
    if (t < 21) g_fmom[t] = 0.f;
    if (t < 64) g_h1sum[t] = 0.f;
    if (t < 128){ g_x3sum[t] = 0.f; g_x3sq[t] = 0.f; }
    if (t == 0) g_cnt = 0u;
}

// ---------------- K1: ball query + feat + feat moments + out1 ----------------
__global__ __launch_bounds__(256) void k_ball(const float* __restrict__ xyz,
                                              const float* __restrict__ points,
                                              const int*   __restrict__ fps,
                                              float* __restrict__ out1) {
    extern __shared__ float sm[];
    float* sx = sm;
    float* sy = sm + NN;
    float* sz = sm + 2*NN;
    int*   fnd = (int*)(sm + 3*NN);   // [8 warps][32]

    int b = blockIdx.y;
    int qbase = blockIdx.x * 32;
    int tid = threadIdx.x;

    for (int i = tid; i < NN; i += 256) {
        sx[i] = xyz[(b*3+0)*NN + i];
        sy[i] = xyz[(b*3+1)*NN + i];
        sz[i] = xyz[(b*3+2)*NN + i];
    }
    __syncthreads();

    int w = tid >> 5, lane = tid & 31;
    int* f = fnd + w*32;
    unsigned lmask = (1u << lane) - 1u;

    float s1[6], s2[21];
    #pragma unroll
    for (int i = 0; i < 6; i++)  s1[i] = 0.f;
    #pragma unroll
    for (int i = 0; i < 21; i++) s2[i] = 0.f;

    for (int qi = 0; qi < 4; qi++) {
        int s = qbase + w*4 + qi;
        int cidx = fps[b*SS + s];
        float cx = sx[cidx], cy = sy[cidx], cz = sz[cidx];
        if (lane == 0) {
            out1[(b*3+0)*SS + s] = cx;
            out1[(b*3+1)*SS + s] = cy;
            out1[(b*3+2)*SS + s] = cz;
        }
        int cnt = 0;
        for (int chunk = 0; chunk < NN/32; chunk++) {
            int j = chunk*32 + lane;
            float dx = __fsub_rn(sx[j], cx);
            float dy = __fsub_rn(sy[j], cy);
            float dz = __fsub_rn(sz[j], cz);
            float d2 = __fadd_rn(__fadd_rn(__fmul_rn(dx,dx), __fmul_rn(dy,dy)),
                                 __fmul_rn(dz,dz));
            bool hit = (d2 <= R2);
            unsigned mask = __ballot_sync(0xffffffffu, hit);
            if (hit) {
                int pos = cnt + __popc(mask & lmask);
                if (pos < 32) f[pos] = j;
            }
            cnt += __popc(mask);
            if (cnt >= 32) break;
        }
        __syncwarp();
        int j = (lane < cnt) ? f[lane] : f[0];
        __syncwarp();

        float fx = sx[j]-cx, fy = sy[j]-cy, fz = sz[j]-cz;
        float p0 = points[(b*3+0)*NN + j];
        float p1 = points[(b*3+1)*NN + j];
        float p2 = points[(b*3+2)*NN + j];

        size_t base = ((size_t)(b*SS + s)*NSAMP + lane) * 8;
        *(float4*)(g_feat + base)     = make_float4(fx, fy, fz, p0);
        *(float4*)(g_feat + base + 4) = make_float4(p1, p2, 0.f, 0.f);

        float fv[6] = {fx, fy, fz, p0, p1, p2};
        int k = 0;
        #pragma unroll
        for (int c = 0; c < 6; c++) {
            s1[c] += fv[c];
            #pragma unroll
            for (int c2 = 0; c2 <= c; c2++) s2[k++] += fv[c]*fv[c2];
        }
    }

    __shared__ float red[27];
    if (tid < 27) red[tid] = 0.f;
    __syncthreads();
    #pragma unroll
    for (int i = 0; i < 6; i++) {
        float v = s1[i];
        for (int off = 16; off; off >>= 1) v += __shfl_down_sync(0xffffffffu, v, off);
        if (lane == 0) atomicAdd(&red[i], v);
    }
    #pragma unroll
    for (int i = 0; i < 21; i++) {
        float v = s2[i];
        for (int off = 16; off; off >>= 1) v += __shfl_down_sync(0xffffffffu, v, off);
        if (lane == 0) atomicAdd(&red[6+i], v);
    }
    __syncthreads();
    if (tid < 6)       atomicAdd(&g_fsum[tid], red[tid]);
    else if (tid < 27) atomicAdd(&g_fmom[tid-6], red[tid]);
}

// ---------------- BN1 fold helper (per-block, into smem) ----------------
static __device__ __forceinline__ void bn1_fold_block(
        const float* __restrict__ W1, const float* __restrict__ g1,
        const float* __restrict__ b1, float* sW1, float* sB1,
        float* sMu /*6*/, float* sC /*36*/, int t) {
    if (t == 0) {
        const float inv = 1.0f / (float)NSAMPLES;
        for (int c = 0; c < 6; c++) sMu[c] = g_fsum[c]*inv;
        int k = 0;
        for (int c = 0; c < 6; c++)
            for (int c2 = 0; c2 <= c; c2++) {
                float v = g_fmom[k++]*inv; sC[c*6+c2] = v; sC[c2*6+c] = v;
            }
    }
    __syncthreads();
    if (t < 64) {
        float w[6];
        #pragma unroll
        for (int c = 0; c < 6; c++) w[c] = W1[t*6+c];
        float mean = 0.f;
        #pragma unroll
        for (int c = 0; c < 6; c++) mean += w[c]*sMu[c];
        float e2 = 0.f;
        #pragma unroll
        for (int c = 0; c < 6; c++) {
            float tt = 0.f;
            #pragma unroll
            for (int c2 = 0; c2 < 6; c2++) tt += sC[c*6+c2]*w[c2];
            e2 += w[c]*tt;
        }
        float var = fmaxf(e2 - mean*mean, 0.f);
        float sc = g1[t]*rsqrtf(var + BNEPS);
        #pragma unroll
        for (int c = 0; c < 6; c++) sW1[t*6+c] = w[c]*sc;
        sB1[t] = b1[t] - mean*sc;
    }
    __syncthreads();
}

// ---------------- K2: stats — h1 mean + SYRK; last block computes BN2 -------
#define P1PAD 134
#define BW 65
__global__ __launch_bounds__(256) void k_stats(const float* __restrict__ W1,
                                               const float* __restrict__ g1,
                                               const float* __restrict__ b1,
                                               const float* __restrict__ W2,
                                               const float* __restrict__ g2,
                                               const float* __restrict__ b2) {
    extern __shared__ float sm[];
    float* sW1  = sm;              // 384
    float* sB1  = sm + 384;        // 64
    float* ssum = sm + 448;        // 64
    float* sMu  = sm + 512;        // 6
    float* sC   = sm + 518;        // 36 (pad to 560)
    float* sH   = sm + 560;        // 64*134 = 8576

    int t = threadIdx.x;
    if (t < 64) ssum[t] = 0.f;
    bn1_fold_block(W1, g1, b1, sW1, sB1, sMu, sC, t);

    int to = t & 15, ts = t >> 4;
    ull accM[16];
    #pragma unroll
    for (int i = 0; i < 16; i++) accM[i] = 0ull;

    const ull* ra[4]; const ull* rb[4];
    #pragma unroll
    for (int i = 0; i < 4; i++) ra[i] = (const ull*)&sH[(ts + 16*i)*P1PAD];
    #pragma unroll
    for (int j = 0; j < 4; j++) rb[j] = (const ull*)&sH[(to + 16*j)*P1PAD];

    for (int tile = blockIdx.x; tile < NTILES; tile += gridDim.x) {
        size_t s0 = (size_t)tile * 128;
        // h1 tile: sample s, 32 channels per thread, layout [k][s]
        {
            int s = t & 127, kb = t >> 7;
            const float* fp = g_feat + (s0 + s)*8;
            float4 f0 = *(const float4*)fp;
            float4 f1 = *(const float4*)(fp + 4);
            float f[6] = {f0.x, f0.y, f0.z, f0.w, f1.x, f1.y};
            #pragma unroll 8
            for (int kk = 0; kk < 32; kk++) {
                int k = kb*32 + kk;
                float a = sB1[k];
                #pragma unroll
                for (int c = 0; c < 6; c++) a += f[c]*sW1[k*6+c];
                sH[k*P1PAD + s] = fmaxf(a, 0.f);
            }
        }
        __syncthreads();
        // per-channel sums
        {
            int k = t & 63, q = t >> 6;
            float local = 0.f;
            #pragma unroll 8
            for (int m = 0; m < 32; m++) local += sH[k*P1PAD + q*32 + m];
            atomicAdd(&ssum[k], local);
        }
        // SYRK: M[a][b] += sum_s h[a][s]*h[b][s], a = ts+16i, b = to+16j
        #pragma unroll 2
        for (int s2 = 0; s2 < 64; s2++) {
            ull ha[4], hb[4];
            #pragma unroll
            for (int i = 0; i < 4; i++) ha[i] = ra[i][s2];
            #pragma unroll
            for (int j = 0; j < 4; j++) hb[j] = rb[j][s2];
            #pragma unroll
            for (int i = 0; i < 4; i++)
                #pragma unroll
                for (int j = 0; j < 4; j++) fma2(accM[i*4+j], ha[i], hb[j]);
        }
        __syncthreads();
    }

    #pragma unroll
    for (int i = 0; i < 4; i++)
        #pragma unroll
        for (int j = 0; j < 4; j++)
            atomicAdd(&g_M[(ts + 16*i)*64 + (to + 16*j)], hadd2(accM[i*4+j]));
    __syncthreads();
    if (t < 64) atomicAdd(&g_h1sum[t], ssum[t]);

    // ---- last-block BN2 tail (replaces the k_bn2 launch) ----
    __threadfence();
    __syncthreads();
    __shared__ unsigned amLast;
    if (t == 0) amLast = (atomicAdd(&g_cnt, 1u) == gridDim.x - 1u) ? 1u : 0u;
    __syncthreads();
    if (!amLast) return;

    // publish BN1-folded params for k_fused (still live in sW1/sB1)
    if (t < 64) {
        #pragma unroll
        for (int c = 0; c < 6; c++) g_W1s[t*6+c] = sW1[t*6+c];
        g_b1s[t] = sB1[t];
    }
    __syncthreads();   // before reusing sm[0..512) for partials

    float* sM    = sH;              // 4096
    float* sW    = sH + 4096;       // 64*65 = 4160
    float* hm    = sH + 8256;       // 64   (8320 <= 8576)
    float* partm = sm;              // 256 (overwrites sW1/sB1 region)
    float* partq = sm + 256;        // 256

    const float inv = 1.0f / (float)NSAMPLES;
    for (int i = t; i < 4096; i += 256) {
        sM[i] = __ldcg(&g_M[i]);                  // L2-coherent (atomics wrote L2)
        sW[(i >> 6)*BW + (i & 63)] = W2[i];
    }
    if (t < 64) hm[t] = __ldcg(&g_h1sum[t]) * inv;
    __syncthreads();

    int o = t & 63, q = t >> 6;
    const float* w = &sW[o*BW];
    float lm = 0.f, lq = 0.f;
    for (int k = q*16; k < q*16 + 16; k++) {
        float wk = w[k];
        lm += wk*hm[k];
        float s = 0.f;
        #pragma unroll 8
        for (int k2 = 0; k2 < 64; k2++) s += sM[k*64 + k2]*w[k2];
        lq += wk*s;
    }
    partm[t] = lm; partq[t] = lq;
    __syncthreads();
    if (t < 64) {
        float m  = partm[t] + partm[t+64] + partm[t+128] + partm[t+192];
        float qv = (partq[t] + partq[t+64] + partq[t+128] + partq[t+192]) * inv;
        float var = fmaxf(qv - m*m, 0.f);
        float sc = g2[t]*rsqrtf(var + BNEPS);
        g_sc2[t] = sc; g_sh2[t] = b2[t] - m*sc;
    }
}

// ---------------- K3: fused feat->h1->x2->bn2/relu->x3 (R5-proven, occ 2) ----
#define WPAD 66
#define HPAD 70
__global__ __launch_bounds__(256, 2) void k_fused(const float* __restrict__ W2,
                                                  const float* __restrict__ W3) {
    extern __shared__ float sm[];
    float* sW1  = sm;                  // 384
    float* sB1  = sm + 384;            // 64
    float* sc2s = sm + 448;            // 64
    float* sh2s = sm + 512;            // 64
    float* csum = sm + 576;            // 128
    float* csq  = sm + 704;            // 128
    float* sW2  = sm + 832;            // 64*66  = 4224
    float* sW3  = sm + 5056;           // 128*66 = 8448
    float* sH   = sm + 13504;          // 128*70 = 8960
    float* rmax = sm + 832;            // reuse sW2 after GEMM1: [16][128]
    float* rmin = sm + 832 + 2048;

    int t = threadIdx.x;
    for (int i = t; i < 384; i += 256) sW1[i] = g_W1s[i];
    if (t < 64) { sB1[t] = g_b1s[t]; sc2s[t] = g_sc2[t]; sh2s[t] = g_sh2[t]; }
    if (t < 128){ csum[t] = 0.f; csq[t] = 0.f; }
    for (int i = t; i < 4096; i += 256) { int o = i >> 6, k = i & 63; sW2[o*WPAD + k] = W2[i]; }
    for (int i = t; i < 8192; i += 256) { int o = i >> 6, k = i & 63; sW3[o*WPAD + k] = W3[i]; }
    __syncthreads();

    size_t s0 = (size_t)blockIdx.x * 128;

    // step A: h1 into sH[s][k] (float2 stores: 8B-aligned for all s)
    {
        int s = t & 127, kb = t >> 7;
        const float* fp = g_feat + (s0 + s)*8;
        float4 f0 = *(const float4*)fp;
        float4 f1 = *(const float4*)(fp + 4);
        float f[6] = {f0.x, f0.y, f0.z, f0.w, f1.x, f1.y};
        float* dst = &sH[s*HPAD + kb*32];
        #pragma unroll 4
        for (int m = 0; m < 16; m++) {
            float2 hv;
            #pragma unroll
            for (int q = 0; q < 2; q++) {
                int k = kb*32 + m*2 + q;
                float a = sB1[k];
                #pragma unroll
                for (int c = 0; c < 6; c++) a += f[c]*sW1[k*6+c];
                (&hv.x)[q] = fmaxf(a, 0.f);
            }
            *(float2*)(dst + m*2) = hv;
        }
    }
    __syncthreads();

    int to = t & 15, ts = t >> 4;
    const ull* hrow[8];
    #pragma unroll
    for (int j = 0; j < 8; j++) hrow[j] = (const ull*)&sH[(ts*8 + j)*HPAD];

    // GEMM1: x2[o][s], o = to + 16i (i<4), s = ts*8+j
    float h2v[4][8];
    {
        ull acc[32];
        #pragma unroll
        for (int i = 0; i < 32; i++) acc[i] = 0ull;
        const ull* wrow[4];
        #pragma unroll
        for (int i = 0; i < 4; i++) wrow[i] = (const ull*)&sW2[(to + 16*i)*WPAD];
        #pragma unroll 2
        for (int k2 = 0; k2 < 32; k2++) {
            ull wv[4], hv[8];
            #pragma unroll
            for (int i = 0; i < 4; i++) wv[i] = wrow[i][k2];
            #pragma unroll
            for (int j = 0; j < 8; j++) hv[j] = hrow[j][k2];
            #pragma unroll
            for (int i = 0; i < 4; i++)
                #pragma unroll
                for (int j = 0; j < 8; j++) fma2(acc[i*8+j], wv[i], hv[j]);
        }
        #pragma unroll
        for (int i = 0; i < 4; i++) {
            int o = to + 16*i;
            float sc = sc2s[o], sh = sh2s[o];
            #pragma unroll
            for (int j = 0; j < 8; j++)
                h2v[i][j] = fmaxf(hadd2(acc[i*8+j])*sc + sh, 0.f);
        }
    }
    __syncthreads();   // all GEMM1 reads of sH done (sW2 also free now)

    // write h2 into sH[s][k]
    #pragma unroll
    for (int i = 0; i < 4; i++) {
        int o = to + 16*i;
        #pragma unroll
        for (int j = 0; j < 8; j++) sH[(ts*8 + j)*HPAD + o] = h2v[i][j];
    }
    __syncthreads();

    // GEMM2: x3[o][s] in two o-halves; o = half*64 + to + 16i
    for (int half = 0; half < 2; half++) {
        ull acc[32];
        #pragma unroll
        for (int i = 0; i < 32; i++) acc[i] = 0ull;
        const ull* wrow[4];
        #pragma unroll
        for (int i = 0; i < 4; i++) wrow[i] = (const ull*)&sW3[(half*64 + to + 16*i)*WPAD];
        #pragma unroll 2
        for (int k2 = 0; k2 < 32; k2++) {
            ull wv[4], hv[8];
            #pragma unroll
            for (int i = 0; i < 4; i++) wv[i] = wrow[i][k2];
            #pragma unroll
            for (int j = 0; j < 8; j++) hv[j] = hrow[j][k2];
            #pragma unroll
            for (int i = 0; i < 4; i++)
                #pragma unroll
                for (int j = 0; j < 8; j++) fma2(acc[i*8+j], wv[i], hv[j]);
        }
        #pragma unroll
        for (int i = 0; i < 4; i++) {
            int o = half*64 + to + 16*i;
            float ps = 0.f, pq = 0.f, mx = -INFINITY, mn = INFINITY;
            #pragma unroll
            for (int j = 0; j < 8; j++) {
                float x = hadd2(acc[i*8+j]);
                ps += x; pq += x*x; mx = fmaxf(mx, x); mn = fminf(mn, x);
            }
            atomicAdd(&csum[o], ps);
            atomicAdd(&csq[o], pq);
            rmax[ts*128 + o] = mx;
            rmin[ts*128 + o] = mn;
        }
    }
    __syncthreads();

    // reduce 4 ts-rows per group (group = 32 samples)
    for (int v = t; v < 512; v += 256) {
        int gq = v >> 7, o = v & 127;
        float mx = rmax[(gq*4+0)*128 + o];
        mx = fmaxf(mx, rmax[(gq*4+1)*128 + o]);
        mx = fmaxf(mx, rmax[(gq*4+2)*128 + o]);
        mx = fmaxf(mx, rmax[(gq*4+3)*128 + o]);
        float mn = rmin[(gq*4+0)*128 + o];
        mn = fminf(mn, rmin[(gq*4+1)*128 + o]);
        mn = fminf(mn, rmin[(gq*4+2)*128 + o]);
        mn = fminf(mn, rmin[(gq*4+3)*128 + o]);
        size_t g = s0/32 + gq;
        g_gmax[g*128 + o] = mx;
        g_gmin[g*128 + o] = mn;
    }
    __syncthreads();
    if (t < 128) { atomicAdd(&g_x3sum[t], csum[t]); atomicAdd(&g_x3sq[t], csq[t]); }
}

// ---------------- K4: bn3 (inline) + relu on group max/min, transposed out ----
__global__ void k_out2(const float* __restrict__ g3, const float* __restrict__ b3,
                       float* __restrict__ out2) {
    __shared__ float tr[32*129];
    __shared__ float ssc[128], ssh[128];
    int b = blockIdx.y;
    int s0 = blockIdx.x * 32;
    int t = threadIdx.x;
    if (t < 128) {
        const float inv = 1.0f / (float)NSAMPLES;
        float m = g_x3sum[t]*inv;
        float v = fmaxf(g_x3sq[t]*inv - m*m, 0.f);
        float sc = g3[t]*rsqrtf(v + BNEPS);
        ssc[t] = sc; ssh[t] = b3[t] - m*sc;
    }
    __syncthreads();
    for (int i = t; i < 32*128; i += 256) {
        int gi = i >> 7, o = i & 127;
        float sc = ssc[o], sh = ssh[o];
        size_t g = (size_t)(b*SS + s0 + gi);
        float v = (sc >= 0.f) ? g_gmax[g*128 + o] : g_gmin[g*128 + o];
        tr[gi*129 + o] = fmaxf(sc*v + sh, 0.f);
    }
    __syncthreads();
    for (int i = t; i < 32*128; i += 256) {
        int o = i >> 5, si = i & 31;
        out2[((size_t)(b*128 + o))*SS + s0 + si] = tr[si*129 + o];
    }
}

// ---------------- launch ----------------
extern "C" void kernel_launch(void* const* d_in, const int* in_sizes, int n_in,
                              void* d_out, int out_size) {
    const float* xyz    = (const float*)d_in[0];
    const float* points = (const float*)d_in[1];
    const int*   fps    = (const int*)  d_in[2];
    const float* W1 = (const float*)d_in[3];
    const float* g1 = (const float*)d_in[4];
    const float* b1 = (const float*)d_in[5];
    const float* W2 = (const float*)d_in[6];
    const float* g2 = (const float*)d_in[7];
    const float* b2 = (const float*)d_in[8];
    const float* W3 = (const float*)d_in[9];
    const float* g3 = (const float*)d_in[10];
    const float* b3 = (const float*)d_in[11];

    float* out1 = (float*)d_out;
    float* out2 = (float*)d_out + (size_t)BB*3*SS;

    const int SMEM_BALL  = (3*NN)*4 + 8*32*4;                    // 99328
    const int SMEM_STATS = (560 + 64*P1PAD)*4;                   // 36544
    const int SMEM_FUSED = (13504 + 128*HPAD)*4;                 // 89856

    cudaFuncSetAttribute(k_ball,  cudaFuncAttributeMaxDynamicSharedMemorySize, SMEM_BALL);
    cudaFuncSetAttribute(k_stats, cudaFuncAttributeMaxDynamicSharedMemorySize, SMEM_STATS);
    cudaFuncSetAttribute(k_fused, cudaFuncAttributeMaxDynamicSharedMemorySize, SMEM_FUSED);

    k_zero<<<1, 256>>>();
    k_ball<<<dim3(SS/32, BB), 256, SMEM_BALL>>>(xyz, points, fps, out1);
    k_stats<<<592, 256, SMEM_STATS>>>(W1, g1, b1, W2, g2, b2);
    k_fused<<<NTILES, 256, SMEM_FUSED>>>(W2, W3);
    k_out2<<<dim3(SS/32, BB), 256>>>(g3, b3, out2);
}

// round 9
// speedup vs baseline: 1.0960x; 1.0010x over previous
#include <cuda_runtime.h>
#include <math.h>
#include <stdint.h>

#define BB 8
#define NN 8192
#define SS 2048
#define NSAMP 32
#define NSAMPLES (BB*SS*NSAMP)   /* 524288 */
#define NGROUPS (BB*SS)          /* 16384  */
#define NTILES (NSAMPLES/128)    /* 4096   */
#define R2 0.04f
#define BNEPS 1e-5f

typedef unsigned long long ull;

// ---------------- device scratch ----------------
__device__ float g_feat[(size_t)NSAMPLES*8];     // [sample][8] (6 used)
__device__ float g_gmax[(size_t)NGROUPS*128];
__device__ float g_gmin[(size_t)NGROUPS*128];
__device__ float g_fsum[6];
__device__ float g_fmom[21];
__device__ float g_M[64*64];                     // sum over samples of h1 h1^T
__device__ float g_h1sum[64];
__device__ float g_x3sum[128], g_x3sq[128];
__device__ float g_W1s[64*6], g_b1s[64];         // BN1 folded into W1
__device__ float g_sc2[64], g_sh2[64];
__device__ unsigned g_cnt;                       // k_stats completion counter

// ---------------- f32x2 helpers ----------------
static __device__ __forceinline__ void fma2(ull& d, ull a, ull b) {
    asm("fma.rn.f32x2 %0, %1, %2, %0;" : "+l"(d) : "l"(a), "l"(b));
}
static __device__ __forceinline__ float hadd2(ull v) {
    float lo, hi;
    asm("mov.b64 {%0,%1}, %2;" : "=f"(lo), "=f"(hi) : "l"(v));
    return lo + hi;
}

// ---------------- K0: zero accumulators ----------------
__global__ void k_zero() {
    int t = threadIdx.x;
    for (int i = t; i < 4096; i += 256) g_M[i] = 0.f;
    if (t < 6)  g_fsum[t] = 0.f;
    if (t < 21) g_fmom[t] = 0.f;
    if (t < 64) g_h1sum[t] = 0.f;
    if (t < 128){ g_x3sum[t] = 0.f; g_x3sq[t] = 0.f; }
    if (t == 0) g_cnt = 0u;
}

// ---------------- K1: ball query + feat + feat moments + out1 ----------------
__global__ __launch_bounds__(256) void k_ball(const float* __restrict__ xyz,
                                              const float* __restrict__ points,
                                              const int*   __restrict__ fps,
                                              float* __restrict__ out1) {
    extern __shared__ float sm[];
    float* sx = sm;
    float* sy = sm + NN;
    float* sz = sm + 2*NN;
    int*   fnd = (int*)(sm + 3*NN);   // [8 warps][32]

    int b = blockIdx.y;
    int qbase = blockIdx.x * 32;
    int tid = threadIdx.x;

    for (int i = tid; i < NN; i += 256) {
        sx[i] = xyz[(b*3+0)*NN + i];
        sy[i] = xyz[(b*3+1)*NN + i];
        sz[i] = xyz[(b*3+2)*NN + i];
    }
    __syncthreads();

    int w = tid >> 5, lane = tid & 31;
    int* f = fnd + w*32;
    unsigned lmask = (1u << lane) - 1u;

    float s1[6], s2[21];
    #pragma unroll
    for (int i = 0; i < 6; i++)  s1[i] = 0.f;
    #pragma unroll
    for (int i = 0; i < 21; i++) s2[i] = 0.f;

    for (int qi = 0; qi < 4; qi++) {
        int s = qbase + w*4 + qi;
        int cidx = fps[b*SS + s];
        float cx = sx[cidx], cy = sy[cidx], cz = sz[cidx];
        if (lane == 0) {
            out1[(b*3+0)*SS + s] = cx;
            out1[(b*3+1)*SS + s] = cy;
            out1[(b*3+2)*SS + s] = cz;
        }
        int cnt = 0;
        for (int chunk = 0; chunk < NN/32; chunk++) {
            int j = chunk*32 + lane;
            float dx = __fsub_rn(sx[j], cx);
            float dy = __fsub_rn(sy[j], cy);
            float dz = __fsub_rn(sz[j], cz);
            float d2 = __fadd_rn(__fadd_rn(__fmul_rn(dx,dx), __fmul_rn(dy,dy)),
                                 __fmul_rn(dz,dz));
            bool hit = (d2 <= R2);
            unsigned mask = __ballot_sync(0xffffffffu, hit);
            if (hit) {
                int pos = cnt + __popc(mask & lmask);
                if (pos < 32) f[pos] = j;
            }
            cnt += __popc(mask);
            if (cnt >= 32) break;
        }
        __syncwarp();
        int j = (lane < cnt) ? f[lane] : f[0];
        __syncwarp();

        float fx = sx[j]-cx, fy = sy[j]-cy, fz = sz[j]-cz;
        float p0 = points[(b*3+0)*NN + j];
        float p1 = points[(b*3+1)*NN + j];
        float p2 = points[(b*3+2)*NN + j];

        size_t base = ((size_t)(b*SS + s)*NSAMP + lane) * 8;
        *(float4*)(g_feat + base)     = make_float4(fx, fy, fz, p0);
        *(float4*)(g_feat + base + 4) = make_float4(p1, p2, 0.f, 0.f);

        float fv[6] = {fx, fy, fz, p0, p1, p2};
        int k = 0;
        #pragma unroll
        for (int c = 0; c < 6; c++) {
            s1[c] += fv[c];
            #pragma unroll
            for (int c2 = 0; c2 <= c; c2++) s2[k++] += fv[c]*fv[c2];
        }
    }

    __shared__ float red[27];
    if (tid < 27) red[tid] = 0.f;
    __syncthreads();
    #pragma unroll
    for (int i = 0; i < 6; i++) {
        float v = s1[i];
        for (int off = 16; off; off >>= 1) v += __shfl_down_sync(0xffffffffu, v, off);
        if (lane == 0) atomicAdd(&red[i], v);
    }
    #pragma unroll
    for (int i = 0; i < 21; i++) {
        float v = s2[i];
        for (int off = 16; off; off >>= 1) v += __shfl_down_sync(0xffffffffu, v, off);
        if (lane == 0) atomicAdd(&red[6+i], v);
    }
    __syncthreads();
    if (tid < 6)       atomicAdd(&g_fsum[tid], red[tid]);
    else if (tid < 27) atomicAdd(&g_fmom[tid-6], red[tid]);
}

// ---------------- BN1 fold helper (per-block, into smem) ----------------
static __device__ __forceinline__ void bn1_fold_block(
        const float* __restrict__ W1, const float* __restrict__ g1,
        const float* __restrict__ b1, float* sW1, float* sB1,
        float* sMu /*6*/, float* sC /*36*/, int t) {
    if (t == 0) {
        const float inv = 1.0f / (float)NSAMPLES;
        for (int c = 0; c < 6; c++) sMu[c] = g_fsum[c]*inv;
        int k = 0;
        for (int c = 0; c < 6; c++)
            for (int c2 = 0; c2 <= c; c2++) {
                float v = g_fmom[k++]*inv; sC[c*6+c2] = v; sC[c2*6+c] = v;
            }
    }
    __syncthreads();
    if (t < 64) {
        float w[6];
        #pragma unroll
        for (int c = 0; c < 6; c++) w[c] = W1[t*6+c];
        float mean = 0.f;
        #pragma unroll
        for (int c = 0; c < 6; c++) mean += w[c]*sMu[c];
        float e2 = 0.f;
        #pragma unroll
        for (int c = 0; c < 6; c++) {
            float tt = 0.f;
            #pragma unroll
            for (int c2 = 0; c2 < 6; c2++) tt += sC[c*6+c2]*w[c2];
            e2 += w[c]*tt;
        }
        float var = fmaxf(e2 - mean*mean, 0.f);
        float sc = g1[t]*rsqrtf(var + BNEPS);
        #pragma unroll
        for (int c = 0; c < 6; c++) sW1[t*6+c] = w[c]*sc;
        sB1[t] = b1[t] - mean*sc;
    }
    __syncthreads();
}

// ---------------- K2: stats — h1 mean + SYRK; last block computes BN2 -------
#define P1PAD 134
#define BW 65
__global__ __launch_bounds__(256) void k_stats(const float* __restrict__ W1,
                                               const float* __restrict__ g1,
                                               const float* __restrict__ b1,
                                               const float* __restrict__ W2,
                                               const float* __restrict__ g2,
                                               const float* __restrict__ b2) {
    extern __shared__ float sm[];
    float* sW1  = sm;              // 384
    float* sB1  = sm + 384;        // 64
    float* ssum = sm + 448;        // 64
    float* sMu  = sm + 512;        // 6
    float* sC   = sm + 518;        // 36 (pad to 560)
    float* sH   = sm + 560;        // 64*134 = 8576

    int t = threadIdx.x;
    if (t < 64) ssum[t] = 0.f;
    bn1_fold_block(W1, g1, b1, sW1, sB1, sMu, sC, t);

    int to = t & 15, ts = t >> 4;
    ull accM[16];
    #pragma unroll
    for (int i = 0; i < 16; i++) accM[i] = 0ull;

    const ull* ra[4]; const ull* rb[4];
    #pragma unroll
    for (int i = 0; i < 4; i++) ra[i] = (const ull*)&sH[(ts + 16*i)*P1PAD];
    #pragma unroll
    for (int j = 0; j < 4; j++) rb[j] = (const ull*)&sH[(to + 16*j)*P1PAD];

    for (int tile = blockIdx.x; tile < NTILES; tile += gridDim.x) {
        size_t s0 = (size_t)tile * 128;
        // h1 tile: sample s, 32 channels per thread, layout [k][s]
        {
            int s = t & 127, kb = t >> 7;
            const float* fp = g_feat + (s0 + s)*8;
            float4 f0 = *(const float4*)fp;
            float4 f1 = *(const float4*)(fp + 4);
            float f[6] = {f0.x, f0.y, f0.z, f0.w, f1.x, f1.y};
            #pragma unroll 8
            for (int kk = 0; kk < 32; kk++) {
                int k = kb*32 + kk;
                float a = sB1[k];
                #pragma unroll
                for (int c = 0; c < 6; c++) a += f[c]*sW1[k*6+c];
                sH[k*P1PAD + s] = fmaxf(a, 0.f);
            }
        }
        __syncthreads();
        // per-channel sums
        {
            int k = t & 63, q = t >> 6;
            float local = 0.f;
            #pragma unroll 8
            for (int m = 0; m < 32; m++) local += sH[k*P1PAD + q*32 + m];
            atomicAdd(&ssum[k], local);
        }
        // SYRK: M[a][b] += sum_s h[a][s]*h[b][s], a = ts+16i, b = to+16j
        #pragma unroll 2
        for (int s2 = 0; s2 < 64; s2++) {
            ull ha[4], hb[4];
            #pragma unroll
            for (int i = 0; i < 4; i++) ha[i] = ra[i][s2];
            #pragma unroll
            for (int j = 0; j < 4; j++) hb[j] = rb[j][s2];
            #pragma unroll
            for (int i = 0; i < 4; i++)
                #pragma unroll
                for (int j = 0; j < 4; j++) fma2(accM[i*4+j], ha[i], hb[j]);
        }
        __syncthreads();
    }

    #pragma unroll
    for (int i = 0; i < 4; i++)
        #pragma unroll
        for (int j = 0; j < 4; j++)
            atomicAdd(&g_M[(ts + 16*i)*64 + (to + 16*j)], hadd2(accM[i*4+j]));
    __syncthreads();
    if (t < 64) atomicAdd(&g_h1sum[t], ssum[t]);

    // ---- last-block BN2 tail (replaces the k_bn2 launch) ----
    __threadfence();
    __syncthreads();
    __shared__ unsigned amLast;
    if (t == 0) amLast = (atomicAdd(&g_cnt, 1u) == gridDim.x - 1u) ? 1u : 0u;
    __syncthreads();
    if (!amLast) return;

    // publish BN1-folded params for k_fused (still live in sW1/sB1)
    if (t < 64) {
        #pragma unroll
        for (int c = 0; c < 6; c++) g_W1s[t*6+c] = sW1[t*6+c];
        g_b1s[t] = sB1[t];
    }
    __syncthreads();   // before reusing sm[0..512) for partials

    float* sM    = sH;              // 4096
    float* sW    = sH + 4096;       // 64*65 = 4160
    float* hm    = sH + 8256;       // 64   (8320 <= 8576)
    float* partm = sm;              // 256 (overwrites sW1/sB1 region)
    float* partq = sm + 256;        // 256

    const float inv = 1.0f / (float)NSAMPLES;
    for (int i = t; i < 4096; i += 256) {
        sM[i] = __ldcg(&g_M[i]);                  // L2-coherent (atomics wrote L2)
        sW[(i >> 6)*BW + (i & 63)] = W2[i];
    }
    if (t < 64) hm[t] = __ldcg(&g_h1sum[t]) * inv;
    __syncthreads();

    int o = t & 63, q = t >> 6;
    const float* w = &sW[o*BW];
    float lm = 0.f, lq = 0.f;
    for (int k = q*16; k < q*16 + 16; k++) {
        float wk = w[k];
        lm += wk*hm[k];
        float s = 0.f;
        #pragma unroll 8
        for (int k2 = 0; k2 < 64; k2++) s += sM[k*64 + k2]*w[k2];
        lq += wk*s;
    }
    partm[t] = lm; partq[t] = lq;
    __syncthreads();
    if (t < 64) {
        float m  = partm[t] + partm[t+64] + partm[t+128] + partm[t+192];
        float qv = (partq[t] + partq[t+64] + partq[t+128] + partq[t+192]) * inv;
        float var = fmaxf(qv - m*m, 0.f);
        float sc = g2[t]*rsqrtf(var + BNEPS);
        g_sc2[t] = sc; g_sh2[t] = b2[t] - m*sc;
    }
}

// ---------------- K3: fused feat->h1->x2->bn2/relu->x3 -----------------------
// 2 tiles per block (weights staged once); h loads via LDS.128 (HPAD=72:
// rows 16B-aligned, h reads are half-warp broadcasts so pad-bank neutrality
// not needed for reads).
#define WPAD 66
#define HPAD 72
__global__ __launch_bounds__(256, 2) void k_fused(const float* __restrict__ W2,
                                                  const float* __restrict__ W3) {
    extern __shared__ float sm[];
    float* sW1  = sm;                  // 384
    float* sB1  = sm + 384;            // 64
    float* sc2s = sm + 448;            // 64
    float* sh2s = sm + 512;            // 64
    float* csum = sm + 576;            // 128
    float* csq  = sm + 704;            // 128
    float* sW2  = sm + 832;            // 64*66  = 4224
    float* sW3  = sm + 5056;           // 128*66 = 8448
    float* rmax = sm + 13504;          // 16*128 = 2048
    float* rmin = sm + 15552;          // 2048
    float* sH   = sm + 17600;          // 128*72 = 9216  (base 70400B, 16B aligned)

    int t = threadIdx.x;
    for (int i = t; i < 384; i += 256) sW1[i] = g_W1s[i];
    if (t < 64) { sB1[t] = g_b1s[t]; sc2s[t] = g_sc2[t]; sh2s[t] = g_sh2[t]; }
    if (t < 128){ csum[t] = 0.f; csq[t] = 0.f; }
    for (int i = t; i < 4096; i += 256) { int o = i >> 6, k = i & 63; sW2[o*WPAD + k] = W2[i]; }
    for (int i = t; i < 8192; i += 256) { int o = i >> 6, k = i & 63; sW3[o*WPAD + k] = W3[i]; }
    __syncthreads();

    int to = t & 15, ts = t >> 4;
    const ulonglong2* hrow[8];
    #pragma unroll
    for (int j = 0; j < 8; j++) hrow[j] = (const ulonglong2*)&sH[(ts*8 + j)*HPAD];

    for (int tt = 0; tt < 2; tt++) {
        size_t s0 = ((size_t)blockIdx.x*2 + tt) * 128;

        // step A: h1 into sH[s][k] (float2 stores: 8B-aligned for all s)
        {
            int s = t & 127, kb = t >> 7;
            const float* fp = g_feat + (s0 + s)*8;
            float4 f0 = *(const float4*)fp;
            float4 f1 = *(const float4*)(fp + 4);
            float f[6] = {f0.x, f0.y, f0.z, f0.w, f1.x, f1.y};
            float* dst = &sH[s*HPAD + kb*32];
            #pragma unroll 4
            for (int m = 0; m < 16; m++) {
                float2 hv;
                #pragma unroll
                for (int q = 0; q < 2; q++) {
                    int k = kb*32 + m*2 + q;
                    float a = sB1[k];
                    #pragma unroll
                    for (int c = 0; c < 6; c++) a += f[c]*sW1[k*6+c];
                    (&hv.x)[q] = fmaxf(a, 0.f);
                }
                *(float2*)(dst + m*2) = hv;
            }
        }
        __syncthreads();

        // GEMM1: x2[o][s], o = to + 16i (i<4), s = ts*8+j
        float h2v[4][8];
        {
            ull acc[32];
            #pragma unroll
            for (int i = 0; i < 32; i++) acc[i] = 0ull;
            const ull* wrow[4];
            #pragma unroll
            for (int i = 0; i < 4; i++) wrow[i] = (const ull*)&sW2[(to + 16*i)*WPAD];
            #pragma unroll 1
            for (int kp = 0; kp < 16; kp++) {
                ulonglong2 hv[8];
                #pragma unroll
                for (int j = 0; j < 8; j++) hv[j] = hrow[j][kp];
                ull wv0[4], wv1[4];
                #pragma unroll
                for (int i = 0; i < 4; i++) { wv0[i] = wrow[i][2*kp]; wv1[i] = wrow[i][2*kp+1]; }
                #pragma unroll
                for (int i = 0; i < 4; i++)
                    #pragma unroll
                    for (int j = 0; j < 8; j++) fma2(acc[i*8+j], wv0[i], hv[j].x);
                #pragma unroll
                for (int i = 0; i < 4; i++)
                    #pragma unroll
                    for (int j = 0; j < 8; j++) fma2(acc[i*8+j], wv1[i], hv[j].y);
            }
            #pragma unroll
            for (int i = 0; i < 4; i++) {
                int o = to + 16*i;
                float sc = sc2s[o], sh = sh2s[o];
                #pragma unroll
                for (int j = 0; j < 8; j++)
                    h2v[i][j] = fmaxf(hadd2(acc[i*8+j])*sc + sh, 0.f);
            }
        }
        __syncthreads();   // all GEMM1 reads of sH done

        // write h2 into sH[s][k]
        #pragma unroll
        for (int i = 0; i < 4; i++) {
            int o = to + 16*i;
            #pragma unroll
            for (int j = 0; j < 8; j++) sH[(ts*8 + j)*HPAD + o] = h2v[i][j];
        }
        __syncthreads();

        // GEMM2: x3[o][s] in two o-halves; o = half*64 + to + 16i
        for (int half = 0; half < 2; half++) {
            ull acc[32];
            #pragma unroll
            for (int i = 0; i < 32; i++) acc[i] = 0ull;
            const ull* wrow[4];
            #pragma unroll
            for (int i = 0; i < 4; i++) wrow[i] = (const ull*)&sW3[(half*64 + to + 16*i)*WPAD];
            #pragma unroll 1
            for (int kp = 0; kp < 16; kp++) {
                ulonglong2 hv[8];
                #pragma unroll
                for (int j = 0; j < 8; j++) hv[j] = hrow[j][kp];
                ull wv0[4], wv1[4];
                #pragma unroll
                for (int i = 0; i < 4; i++) { wv0[i] = wrow[i][2*kp]; wv1[i] = wrow[i][2*kp+1]; }
                #pragma unroll
                for (int i = 0; i < 4; i++)
                    #pragma unroll
                    for (int j = 0; j < 8; j++) fma2(acc[i*8+j], wv0[i], hv[j].x);
                #pragma unroll
                for (int i = 0; i < 4; i++)
                    #pragma unroll
                    for (int j = 0; j < 8; j++) fma2(acc[i*8+j], wv1[i], hv[j].y);
            }
            #pragma unroll
            for (int i = 0; i < 4; i++) {
                int o = half*64 + to + 16*i;
                float ps = 0.f, pq = 0.f, mx = -INFINITY, mn = INFINITY;
                #pragma unroll
                for (int j = 0; j < 8; j++) {
                    float x = hadd2(acc[i*8+j]);
                    ps += x; pq += x*x; mx = fmaxf(mx, x); mn = fminf(mn, x);
                }
                atomicAdd(&csum[o], ps);
                atomicAdd(&csq[o], pq);
                rmax[ts*128 + o] = mx;
                rmin[ts*128 + o] = mn;
            }
        }
        __syncthreads();

        // reduce 4 ts-rows per group (group = 32 samples)
        for (int v = t; v < 512; v += 256) {
            int gq = v >> 7, o = v & 127;
            float mx = rmax[(gq*4+0)*128 + o];
            mx = fmaxf(mx, rmax[(gq*4+1)*128 + o]);
            mx = fmaxf(mx, rmax[(gq*4+2)*128 + o]);
            mx = fmaxf(mx, rmax[(gq*4+3)*128 + o]);
            float mn = rmin[(gq*4+0)*128 + o];
            mn = fminf(mn, rmin[(gq*4+1)*128 + o]);
            mn = fminf(mn, rmin[(gq*4+2)*128 + o]);
            mn = fminf(mn, rmin[(gq*4+3)*128 + o]);
            size_t g = s0/32 + gq;
            g_gmax[g*128 + o] = mx;
            g_gmin[g*128 + o] = mn;
        }
        // no extra sync needed: next tile's step A touches only sH (readers of
        // sH finished before the sync above), and rmax/rmin aren't rewritten
        // until after two more barriers.
    }
    __syncthreads();
    if (t < 128) { atomicAdd(&g_x3sum[t], csum[t]); atomicAdd(&g_x3sq[t], csq[t]); }
}

// ---------------- K4: bn3 (inline) + relu on group max/min, transposed out ----
__global__ void k_out2(const float* __restrict__ g3, const float* __restrict__ b3,
                       float* __restrict__ out2) {
    __shared__ float tr[32*129];
    __shared__ float ssc[128], ssh[128];
    int b = blockIdx.y;
    int s0 = blockIdx.x * 32;
    int t = threadIdx.x;
    if (t < 128) {
        const float inv = 1.0f / (float)NSAMPLES;
        float m = g_x3sum[t]*inv;
        float v = fmaxf(g_x3sq[t]*inv - m*m, 0.f);
        float sc = g3[t]*rsqrtf(v + BNEPS);
        ssc[t] = sc; ssh[t] = b3[t] - m*sc;
    }
    __syncthreads();
    for (int i = t; i < 32*128; i += 256) {
        int gi = i >> 7, o = i & 127;
        float sc = ssc[o], sh = ssh[o];
        size_t g = (size_t)(b*SS + s0 + gi);
        float v = (sc >= 0.f) ? g_gmax[g*128 + o] : g_gmin[g*128 + o];
        tr[gi*129 + o] = fmaxf(sc*v + sh, 0.f);
    }
    __syncthreads();
    for (int i = t; i < 32*128; i += 256) {
        int o = i >> 5, si = i & 31;
        out2[((size_t)(b*128 + o))*SS + s0 + si] = tr[si*129 + o];
    }
}

// ---------------- launch ----------------
extern "C" void kernel_launch(void* const* d_in, const int* in_sizes, int n_in,
                              void* d_out, int out_size) {
    const float* xyz    = (const float*)d_in[0];
    const float* points = (const float*)d_in[1];
    const int*   fps    = (const int*)  d_in[2];
    const float* W1 = (const float*)d_in[3];
    const float* g1 = (const float*)d_in[4];
    const float* b1 = (const float*)d_in[5];
    const float* W2 = (const float*)d_in[6];
    const float* g2 = (const float*)d_in[7];
    const float* b2 = (const float*)d_in[8];
    const float* W3 = (const float*)d_in[9];
    const float* g3 = (const float*)d_in[10];
    const float* b3 = (const float*)d_in[11];

    float* out1 = (float*)d_out;
    float* out2 = (float*)d_out + (size_t)BB*3*SS;

    const int SMEM_BALL  = (3*NN)*4 + 8*32*4;                    // 99328
    const int SMEM_STATS = (560 + 64*P1PAD)*4;                   // 36544
    const int SMEM_FUSED = (17600 + 128*HPAD)*4;                 // 107264

    cudaFuncSetAttribute(k_ball,  cudaFuncAttributeMaxDynamicSharedMemorySize, SMEM_BALL);
    cudaFuncSetAttribute(k_stats, cudaFuncAttributeMaxDynamicSharedMemorySize, SMEM_STATS);
    cudaFuncSetAttribute(k_fused, cudaFuncAttributeMaxDynamicSharedMemorySize, SMEM_FUSED);

    k_zero<<<1, 256>>>();
    k_ball<<<dim3(SS/32, BB), 256, SMEM_BALL>>>(xyz, points, fps, out1);
    k_stats<<<592, 256, SMEM_STATS>>>(W1, g1, b1, W2, g2, b2);
    k_fused<<<NTILES/2, 256, SMEM_FUSED>>>(W2, W3);
    k_out2<<<dim3(SS/32, BB), 256>>>(g3, b3, out2);
}

// round 11
// speedup vs baseline: 1.5257x; 1.3921x over previous
#include <cuda_runtime.h>
#include <cuda_fp16.h>
#include <math.h>
#include <stdint.h>

#define BB 8
#define NN 8192
#define SS 2048
#define NSAMP 32
#define NSAMPLES (BB*SS*NSAMP)   /* 524288 */
#define NGROUPS (BB*SS)          /* 16384  */
#define NTILES (NSAMPLES/128)    /* 4096   */
#define R2 0.04f
#define BNEPS 1e-5f

typedef unsigned long long ull;

// ---------------- device scratch ----------------
__device__ float g_feat[(size_t)NSAMPLES*8];
__device__ float g_gmax[(size_t)NGROUPS*128];
__device__ float g_gmin[(size_t)NGROUPS*128];
__device__ float g_fsum[6];
__device__ float g_fmom[21];
__device__ float g_M[64*64];
__device__ float g_h1sum[64];
__device__ float g_x3sum[128], g_x3sq[128];
__device__ float g_W1s[64*6], g_b1s[64];
__device__ float g_sc2[64], g_sh2[64];
__device__ unsigned g_cnt;

// ---------------- f32x2 helpers (k_stats) ----------------
static __device__ __forceinline__ void fma2(ull& d, ull a, ull b) {
    asm("fma.rn.f32x2 %0, %1, %2, %0;" : "+l"(d) : "l"(a), "l"(b));
}
static __device__ __forceinline__ float hadd2(ull v) {
    float lo, hi;
    asm("mov.b64 {%0,%1}, %2;" : "=f"(lo), "=f"(hi) : "l"(v));
    return lo + hi;
}

// ---------------- mma.sync helpers ----------------
static __device__ __forceinline__ uint32_t smem_to_u32(const void* p) {
    uint32_t a;
    asm("{ .reg .u64 tmp; cvta.to.shared.u64 tmp, %1; cvt.u32.u64 %0, tmp; }"
        : "=r"(a) : "l"(p));
    return a;
}
static __device__ __forceinline__ uint32_t swz(uint32_t off) {
    return off ^ ((off >> 3) & 0x70);
}
static __device__ __forceinline__ void ldsm_x4(uint32_t (&a)[4], uint32_t addr) {
    asm volatile("ldmatrix.sync.aligned.m8n8.x4.shared.b16 {%0,%1,%2,%3}, [%4];"
        : "=r"(a[0]), "=r"(a[1]), "=r"(a[2]), "=r"(a[3]) : "r"(addr));
}
static __device__ __forceinline__ void ldsm_x2(uint32_t (&b)[2], uint32_t addr) {
    asm volatile("ldmatrix.sync.aligned.m8n8.x2.shared.b16 {%0,%1}, [%2];"
        : "=r"(b[0]), "=r"(b[1]) : "r"(addr));
}
static __device__ __forceinline__ void mma16816(float (&d)[4], const uint32_t (&a)[4],
                                                const uint32_t (&b)[2]) {
    asm volatile("mma.sync.aligned.m16n8k16.row.col.f32.f16.f16.f32 "
        "{%0,%1,%2,%3}, {%4,%5,%6,%7}, {%8,%9}, {%0,%1,%2,%3};"
        : "+f"(d[0]), "+f"(d[1]), "+f"(d[2]), "+f"(d[3])
        : "r"(a[0]), "r"(a[1]), "r"(a[2]), "r"(a[3]), "r"(b[0]), "r"(b[1]));
}

// ---------------- K0: zero accumulators ----------------
__global__ void k_zero() {
    int t = threadIdx.x;
    for (int i = t; i < 4096; i += 256) g_M[i] = 0.f;
    if (t < 6)  g_fsum[t] = 0.f;
    if (t < 21) g_fmom[t] = 0.f;
    if (t < 64) g_h1sum[t] = 0.f;
    if (t < 128){ g_x3sum[t] = 0.f; g_x3sq[t] = 0.f; }
    if (t == 0) g_cnt = 0u;
}

// ---------------- K1: ball query + feat + feat moments + out1 ----------------
__global__ __launch_bounds__(256) void k_ball(const float* __restrict__ xyz,
                                              const float* __restrict__ points,
                                              const int*   __restrict__ fps,
                                              float* __restrict__ out1) {
    extern __shared__ float sm[];
    float* sx = sm;
    float* sy = sm + NN;
    float* sz = sm + 2*NN;
    int*   fnd = (int*)(sm + 3*NN);

    int b = blockIdx.y;
    int qbase = blockIdx.x * 32;
    int tid = threadIdx.x;

    for (int i = tid; i < NN; i += 256) {
        sx[i] = xyz[(b*3+0)*NN + i];
        sy[i] = xyz[(b*3+1)*NN + i];
        sz[i] = xyz[(b*3+2)*NN + i];
    }
    __syncthreads();

    int w = tid >> 5, lane = tid & 31;
    int* f = fnd + w*32;
    unsigned lmask = (1u << lane) - 1u;

    float s1[6], s2[21];
    #pragma unroll
    for (int i = 0; i < 6; i++)  s1[i] = 0.f;
    #pragma unroll
    for (int i = 0; i < 21; i++) s2[i] = 0.f;

    for (int qi = 0; qi < 4; qi++) {
        int s = qbase + w*4 + qi;
        int cidx = fps[b*SS + s];
        float cx = sx[cidx], cy = sy[cidx], cz = sz[cidx];
        if (lane == 0) {
            out1[(b*3+0)*SS + s] = cx;
            out1[(b*3+1)*SS + s] = cy;
            out1[(b*3+2)*SS + s] = cz;
        }
        int cnt = 0;
        for (int chunk = 0; chunk < NN/32; chunk++) {
            int j = chunk*32 + lane;
            float dx = __fsub_rn(sx[j], cx);
            float dy = __fsub_rn(sy[j], cy);
            float dz = __fsub_rn(sz[j], cz);
            float d2 = __fadd_rn(__fadd_rn(__fmul_rn(dx,dx), __fmul_rn(dy,dy)),
                                 __fmul_rn(dz,dz));
            bool hit = (d2 <= R2);
            unsigned mask = __ballot_sync(0xffffffffu, hit);
            if (hit) {
                int pos = cnt + __popc(mask & lmask);
                if (pos < 32) f[pos] = j;
            }
            cnt += __popc(mask);
            if (cnt >= 32) break;
        }
        __syncwarp();
        int j = (lane < cnt) ? f[lane] : f[0];
        __syncwarp();

        float fx = sx[j]-cx, fy = sy[j]-cy, fz = sz[j]-cz;
        float p0 = points[(b*3+0)*NN + j];
        float p1 = points[(b*3+1)*NN + j];
        float p2 = points[(b*3+2)*NN + j];

        size_t base = ((size_t)(b*SS + s)*NSAMP + lane) * 8;
        *(float4*)(g_feat + base)     = make_float4(fx, fy, fz, p0);
        *(float4*)(g_feat + base + 4) = make_float4(p1, p2, 0.f, 0.f);

        float fv[6] = {fx, fy, fz, p0, p1, p2};
        int k = 0;
        #pragma unroll
        for (int c = 0; c < 6; c++) {
            s1[c] += fv[c];
            #pragma unroll
            for (int c2 = 0; c2 <= c; c2++) s2[k++] += fv[c]*fv[c2];
        }
    }

    __shared__ float red[27];
    if (tid < 27) red[tid] = 0.f;
    __syncthreads();
    #pragma unroll
    for (int i = 0; i < 6; i++) {
        float v = s1[i];
        for (int off = 16; off; off >>= 1) v += __shfl_down_sync(0xffffffffu, v, off);
        if (lane == 0) atomicAdd(&red[i], v);
    }
    #pragma unroll
    for (int i = 0; i < 21; i++) {
        float v = s2[i];
        for (int off = 16; off; off >>= 1) v += __shfl_down_sync(0xffffffffu, v, off);
        if (lane == 0) atomicAdd(&red[6+i], v);
    }
    __syncthreads();
    if (tid < 6)       atomicAdd(&g_fsum[tid], red[tid]);
    else if (tid < 27) atomicAdd(&g_fmom[tid-6], red[tid]);
}

// ---------------- BN1 fold helper ----------------
static __device__ __forceinline__ void bn1_fold_block(
        const float* __restrict__ W1, const float* __restrict__ g1,
        const float* __restrict__ b1, float* sW1, float* sB1,
        float* sMu, float* sC, int t) {
    if (t == 0) {
        const float inv = 1.0f / (float)NSAMPLES;
        for (int c = 0; c < 6; c++) sMu[c] = g_fsum[c]*inv;
        int k = 0;
        for (int c = 0; c < 6; c++)
            for (int c2 = 0; c2 <= c; c2++) {
                float v = g_fmom[k++]*inv; sC[c*6+c2] = v; sC[c2*6+c] = v;
            }
    }
    __syncthreads();
    if (t < 64) {
        float w[6];
        #pragma unroll
        for (int c = 0; c < 6; c++) w[c] = W1[t*6+c];
        float mean = 0.f;
        #pragma unroll
        for (int c = 0; c < 6; c++) mean += w[c]*sMu[c];
        float e2 = 0.f;
        #pragma unroll
        for (int c = 0; c < 6; c++) {
            float tt = 0.f;
            #pragma unroll
            for (int c2 = 0; c2 < 6; c2++) tt += sC[c*6+c2]*w[c2];
            e2 += w[c]*tt;
        }
        float var = fmaxf(e2 - mean*mean, 0.f);
        float sc = g1[t]*rsqrtf(var + BNEPS);
        #pragma unroll
        for (int c = 0; c < 6; c++) sW1[t*6+c] = w[c]*sc;
        sB1[t] = b1[t] - mean*sc;
    }
    __syncthreads();
}

// ---------------- K2: stats — h1 mean + SYRK; last block computes BN2 -------
#define P1PAD 134
#define BW 65
__global__ __launch_bounds__(256) void k_stats(const float* __restrict__ W1,
                                               const float* __restrict__ g1,
                                               const float* __restrict__ b1,
                                               const float* __restrict__ W2,
                                               const float* __restrict__ g2,
                                               const float* __restrict__ b2) {
    extern __shared__ float sm[];
    float* sW1  = sm;
    float* sB1  = sm + 384;
    float* ssum = sm + 448;
    float* sMu  = sm + 512;
    float* sC   = sm + 518;
    float* sH   = sm + 560;

    int t = threadIdx.x;
    if (t < 64) ssum[t] = 0.f;
    bn1_fold_block(W1, g1, b1, sW1, sB1, sMu, sC, t);

    int to = t & 15, ts = t >> 4;
    ull accM[16];
    #pragma unroll
    for (int i = 0; i < 16; i++) accM[i] = 0ull;

    const ull* ra[4]; const ull* rb[4];
    #pragma unroll
    for (int i = 0; i < 4; i++) ra[i] = (const ull*)&sH[(ts + 16*i)*P1PAD];
    #pragma unroll
    for (int j = 0; j < 4; j++) rb[j] = (const ull*)&sH[(to + 16*j)*P1PAD];

    for (int tile = blockIdx.x; tile < NTILES; tile += gridDim.x) {
        size_t s0 = (size_t)tile * 128;
        {
            int s = t & 127, kb = t >> 7;
            const float* fp = g_feat + (s0 + s)*8;
            float4 f0 = *(const float4*)fp;
            float4 f1 = *(const float4*)(fp + 4);
            float f[6] = {f0.x, f0.y, f0.z, f0.w, f1.x, f1.y};
            #pragma unroll 8
            for (int kk = 0; kk < 32; kk++) {
                int k = kb*32 + kk;
                float a = sB1[k];
                #pragma unroll
                for (int c = 0; c < 6; c++) a += f[c]*sW1[k*6+c];
                sH[k*P1PAD + s] = fmaxf(a, 0.f);
            }
        }
        __syncthreads();
        {
            int k = t & 63, q = t >> 6;
            float local = 0.f;
            #pragma unroll 8
            for (int m = 0; m < 32; m++) local += sH[k*P1PAD + q*32 + m];
            atomicAdd(&ssum[k], local);
        }
        #pragma unroll 2
        for (int s2 = 0; s2 < 64; s2++) {
            ull ha[4], hb[4];
            #pragma unroll
            for (int i = 0; i < 4; i++) ha[i] = ra[i][s2];
            #pragma unroll
            for (int j = 0; j < 4; j++) hb[j] = rb[j][s2];
            #pragma unroll
            for (int i = 0; i < 4; i++)
                #pragma unroll
                for (int j = 0; j < 4; j++) fma2(accM[i*4+j], ha[i], hb[j]);
        }
        __syncthreads();
    }

    #pragma unroll
    for (int i = 0; i < 4; i++)
        #pragma unroll
        for (int j = 0; j < 4; j++)
            atomicAdd(&g_M[(ts + 16*i)*64 + (to + 16*j)], hadd2(accM[i*4+j]));
    __syncthreads();
    if (t < 64) atomicAdd(&g_h1sum[t], ssum[t]);

    __threadfence();
    __syncthreads();
    __shared__ unsigned amLast;
    if (t == 0) amLast = (atomicAdd(&g_cnt, 1u) == gridDim.x - 1u) ? 1u : 0u;
    __syncthreads();
    if (!amLast) return;

    if (t < 64) {
        #pragma unroll
        for (int c = 0; c < 6; c++) g_W1s[t*6+c] = sW1[t*6+c];
        g_b1s[t] = sB1[t];
    }
    __syncthreads();

    float* sM    = sH;
    float* sW    = sH + 4096;
    float* hm    = sH + 8256;
    float* partm = sm;
    float* partq = sm + 256;

    const float inv = 1.0f / (float)NSAMPLES;
    for (int i = t; i < 4096; i += 256) {
        sM[i] = __ldcg(&g_M[i]);
        sW[(i >> 6)*BW + (i & 63)] = W2[i];
    }
    if (t < 64) hm[t] = __ldcg(&g_h1sum[t]) * inv;
    __syncthreads();

    int o = t & 63, q = t >> 6;
    const float* w = &sW[o*BW];
    float lm = 0.f, lq = 0.f;
    for (int k = q*16; k < q*16 + 16; k++) {
        float wk = w[k];
        lm += wk*hm[k];
        float s = 0.f;
        #pragma unroll 8
        for (int k2 = 0; k2 < 64; k2++) s += sM[k*64 + k2]*w[k2];
        lq += wk*s;
    }
    partm[t] = lm; partq[t] = lq;
    __syncthreads();
    if (t < 64) {
        float m  = partm[t] + partm[t+64] + partm[t+128] + partm[t+192];
        float qv = (partq[t] + partq[t+64] + partq[t+128] + partq[t+192]) * inv;
        float var = fmaxf(qv - m*m, 0.f);
        float sc = g2[t]*rsqrtf(var + BNEPS);
        g_sc2[t] = sc; g_sh2[t] = b2[t] - m*sc;
    }
}

// ---------------- K3: HMMA fused layer (fp16 mma.sync, fp32 accum) ----------
// 128-sample tile per block, 8 warps; warp w owns samples [w*16, w*16+16).
// GEMM1: D1[s][o] = h1[s][:]·W2[o][:]; epilogue bn2+relu -> fp16 h2 (same rows).
// GEMM2: D2[s][o2] = h2[s][:]·W3[o2][:]; butterfly-reduce for group max/min+stats.
// All fp16 tiles: 128B rows (64 halves), SW128-swizzled -> conflict-free ldmatrix.
#define SM_W2H 4096
#define SM_W3H 12288
#define SM_HB  28672
#define SM_RMX 45056
#define SM_RMN 49152
#define SM_MMA_TOTAL 53248

__global__ __launch_bounds__(256, 2) void k_mma(const float* __restrict__ W2,
                                                const float* __restrict__ W3) {
    extern __shared__ char smc[];
    float* smf = (float*)smc;
    uint32_t sbase = smem_to_u32(smc);
    int t = threadIdx.x, w = t >> 5, lane = t & 31;

    float* sW1  = smf;          // 384
    float* sB1  = smf + 384;    // 64
    float* sc2s = smf + 448;    // 64
    float* sh2s = smf + 512;    // 64
    float* csum = smf + 576;    // 128
    float* csq  = smf + 704;    // 128 (ends 832 floats = 3328 B < 4096)
    float* rmax = (float*)(smc + SM_RMX);   // [8 warps][128]
    float* rmin = (float*)(smc + SM_RMN);

    for (int i = t; i < 384; i += 256) sW1[i] = g_W1s[i];
    if (t < 64) { sB1[t] = g_b1s[t]; sc2s[t] = g_sc2[t]; sh2s[t] = g_sh2[t]; }
    if (t < 128){ csum[t] = 0.f; csq[t] = 0.f; }
    for (int i = t; i < 2048; i += 256) {
        int o = i >> 5, kk = (i & 31)*2;
        __half2 hv = __floats2half2_rn(W2[o*64 + kk], W2[o*64 + kk + 1]);
        *(uint32_t*)(smc + SM_W2H + swz((uint32_t)(o*128 + kk*2))) = *(uint32_t*)&hv;
    }
    for (int i = t; i < 4096; i += 256) {
        int o = i >> 5, kk = (i & 31)*2;
        __half2 hv = __floats2half2_rn(W3[o*64 + kk], W3[o*64 + kk + 1]);
        *(uint32_t*)(smc + SM_W3H + swz((uint32_t)(o*128 + kk*2))) = *(uint32_t*)&hv;
    }

    size_t s0 = (size_t)blockIdx.x * 128;

    // step A: h1 fp32 -> fp16 swizzled; 2 threads per sample (kb halves)
    {
        int srow = w*16 + (lane >> 1), kb = lane & 1;
        const float* fp = g_feat + (s0 + srow)*8;
        float4 f0 = *(const float4*)fp;
        float4 f1 = *(const float4*)(fp + 4);
        float f[6] = {f0.x, f0.y, f0.z, f0.w, f1.x, f1.y};
        #pragma unroll
        for (int m = 0; m < 4; m++) {
            uint32_t pk[4];
            #pragma unroll
            for (int q = 0; q < 4; q++) {
                int k = kb*32 + m*8 + q*2;
                float a0 = sB1[k], a1 = sB1[k+1];
                #pragma unroll
                for (int c = 0; c < 6; c++) {
                    a0 += f[c]*sW1[k*6+c];
                    a1 += f[c]*sW1[(k+1)*6+c];
                }
                __half2 hv = __floats2half2_rn(fmaxf(a0, 0.f), fmaxf(a1, 0.f));
                pk[q] = *(uint32_t*)&hv;
            }
            *(uint4*)(smc + SM_HB + swz((uint32_t)(srow*128 + kb*64 + m*16))) =
                make_uint4(pk[0], pk[1], pk[2], pk[3]);
        }
    }
    __syncthreads();

    int m0 = w*16;
    uint32_t hbB = sbase + SM_HB, w2B = sbase + SM_W2H, w3B = sbase + SM_W3H;
    int arow = m0 + (lane & 15);
    int acolb = ((lane >> 4) & 1) * 16;
    int ln = lane & 15;
    int brow = ln & 7;
    int bcolb = ((ln >> 3) & 1) * 16;

    // GEMM1: 8 n-tiles (o), K=64
    float acc1[8][4];
    #pragma unroll
    for (int j = 0; j < 8; j++)
        #pragma unroll
        for (int i = 0; i < 4; i++) acc1[j][i] = 0.f;
    #pragma unroll
    for (int ks = 0; ks < 4; ks++) {
        int k0b = ks*32;
        uint32_t a[4];
        ldsm_x4(a, hbB + swz((uint32_t)(arow*128 + k0b + acolb)));
        #pragma unroll
        for (int j = 0; j < 8; j++) {
            uint32_t b[2];
            ldsm_x2(b, w2B + swz((uint32_t)((8*j + brow)*128 + k0b + bcolb)));
            mma16816(acc1[j], a, b);
        }
    }
    __syncwarp();
    // epilogue1: bn2+relu -> fp16 h2 into own rows
    {
        int r0 = m0 + (lane >> 2);
        #pragma unroll
        for (int j = 0; j < 8; j++) {
            int o = 8*j + 2*(lane & 3);
            float sc0 = sc2s[o], sh0 = sh2s[o], sc1 = sc2s[o+1], sh1 = sh2s[o+1];
            float y0 = fmaxf(acc1[j][0]*sc0 + sh0, 0.f);
            float y1 = fmaxf(acc1[j][1]*sc1 + sh1, 0.f);
            float y2 = fmaxf(acc1[j][2]*sc0 + sh0, 0.f);
            float y3 = fmaxf(acc1[j][3]*sc1 + sh1, 0.f);
            __half2 h01 = __floats2half2_rn(y0, y1);
            __half2 h23 = __floats2half2_rn(y2, y3);
            *(uint32_t*)(smc + SM_HB + swz((uint32_t)(r0*128 + o*2)))     = *(uint32_t*)&h01;
            *(uint32_t*)(smc + SM_HB + swz((uint32_t)((r0+8)*128 + o*2))) = *(uint32_t*)&h23;
        }
    }
    __syncwarp();

    // GEMM2: 16 n-tiles (o2), K=64
    float acc2[16][4];
    #pragma unroll
    for (int j = 0; j < 16; j++)
        #pragma unroll
        for (int i = 0; i < 4; i++) acc2[j][i] = 0.f;
    #pragma unroll
    for (int ks = 0; ks < 4; ks++) {
        int k0b = ks*32;
        uint32_t a[4];
        ldsm_x4(a, hbB + swz((uint32_t)(arow*128 + k0b + acolb)));
        #pragma unroll
        for (int j = 0; j < 16; j++) {
            uint32_t b[2];
            ldsm_x2(b, w3B + swz((uint32_t)((8*j + brow)*128 + k0b + bcolb)));
            mma16816(acc2[j], a, b);
        }
    }

    // epilogue2: butterfly over the 8 row-groups (16 samples of this warp)
    #pragma unroll
    for (int j = 0; j < 16; j++) {
        float d0 = acc2[j][0], d1 = acc2[j][1], d2 = acc2[j][2], d3 = acc2[j][3];
        float mx0 = fmaxf(d0, d2), mx1 = fmaxf(d1, d3);
        float mn0 = fminf(d0, d2), mn1 = fminf(d1, d3);
        float ps0 = d0 + d2, ps1 = d1 + d3;
        float pq0 = d0*d0 + d2*d2, pq1 = d1*d1 + d3*d3;
        #pragma unroll
        for (int off = 4; off < 32; off <<= 1) {
            mx0 = fmaxf(mx0, __shfl_xor_sync(0xffffffffu, mx0, off));
            mx1 = fmaxf(mx1, __shfl_xor_sync(0xffffffffu, mx1, off));
            mn0 = fminf(mn0, __shfl_xor_sync(0xffffffffu, mn0, off));
            mn1 = fminf(mn1, __shfl_xor_sync(0xffffffffu, mn1, off));
            ps0 += __shfl_xor_sync(0xffffffffu, ps0, off);
            ps1 += __shfl_xor_sync(0xffffffffu, ps1, off);
            pq0 += __shfl_xor_sync(0xffffffffu, pq0, off);
            pq1 += __shfl_xor_sync(0xffffffffu, pq1, off);
        }
        if (lane < 4) {
            int o = 8*j + 2*lane;
            rmax[w*128 + o]     = mx0;
            rmax[w*128 + o + 1] = mx1;
            rmin[w*128 + o]     = mn0;
            rmin[w*128 + o + 1] = mn1;
            atomicAdd(&csum[o],   ps0);
            atomicAdd(&csum[o+1], ps1);
            atomicAdd(&csq[o],    pq0);
            atomicAdd(&csq[o+1],  pq1);
        }
    }
    __syncthreads();

    // combine warp pairs into 32-sample groups
    for (int v = t; v < 512; v += 256) {
        int g = v >> 7, o = v & 127;
        float mx = fmaxf(rmax[(2*g)*128 + o], rmax[(2*g+1)*128 + o]);
        float mn = fminf(rmin[(2*g)*128 + o], rmin[(2*g+1)*128 + o]);
        g_gmax[(s0/32 + g)*128 + o] = mx;
        g_gmin[(s0/32 + g)*128 + o] = mn;
    }
    if (t < 128) { atomicAdd(&g_x3sum[t], csum[t]); atomicAdd(&g_x3sq[t], csq[t]); }
}

// ---------------- K4: bn3 (inline) + relu on group max/min, transposed out ----
__global__ void k_out2(const float* __restrict__ g3, const float* __restrict__ b3,
                       float* __restrict__ out2) {
    __shared__ float tr[32*129];
    __shared__ float ssc[128], ssh[128];
    int b = blockIdx.y;
    int s0 = blockIdx.x * 32;
    int t = threadIdx.x;
    if (t < 128) {
        const float inv = 1.0f / (float)NSAMPLES;
        float m = g_x3sum[t]*inv;
        float v = fmaxf(g_x3sq[t]*inv - m*m, 0.f);
        float sc = g3[t]*rsqrtf(v + BNEPS);
        ssc[t] = sc; ssh[t] = b3[t] - m*sc;
    }
    __syncthreads();
    for (int i = t; i < 32*128; i += 256) {
        int gi = i >> 7, o = i & 127;
        float sc = ssc[o], sh = ssh[o];
        size_t g = (size_t)(b*SS + s0 + gi);
        float v = (sc >= 0.f) ? g_gmax[g*128 + o] : g_gmin[g*128 + o];
        tr[gi*129 + o] = fmaxf(sc*v + sh, 0.f);
    }
    __syncthreads();
    for (int i = t; i < 32*128; i += 256) {
        int o = i >> 5, si = i & 31;
        out2[((size_t)(b*128 + o))*SS + s0 + si] = tr[si*129 + o];
    }
}

// ---------------- launch ----------------
extern "C" void kernel_launch(void* const* d_in, const int* in_sizes, int n_in,
                              void* d_out, int out_size) {
    const float* xyz    = (const float*)d_in[0];
    const float* points = (const float*)d_in[1];
    const int*   fps    = (const int*)  d_in[2];
    const float* W1 = (const float*)d_in[3];
    const float* g1 = (const float*)d_in[4];
    const float* b1 = (const float*)d_in[5];
    const float* W2 = (const float*)d_in[6];
    const float* g2 = (const float*)d_in[7];
    const float* b2 = (const float*)d_in[8];
    const float* W3 = (const float*)d_in[9];
    const float* g3 = (const float*)d_in[10];
    const float* b3 = (const float*)d_in[11];

    float* out1 = (float*)d_out;
    float* out2 = (float*)d_out + (size_t)BB*3*SS;

    const int SMEM_BALL  = (3*NN)*4 + 8*32*4;
    const int SMEM_STATS = (560 + 64*P1PAD)*4;

    cudaFuncSetAttribute(k_ball,  cudaFuncAttributeMaxDynamicSharedMemorySize, SMEM_BALL);
    cudaFuncSetAttribute(k_stats, cudaFuncAttributeMaxDynamicSharedMemorySize, SMEM_STATS);
    cudaFuncSetAttribute(k_mma,   cudaFuncAttributeMaxDynamicSharedMemorySize, SM_MMA_TOTAL);

    k_zero<<<1, 256>>>();
    k_ball<<<dim3(SS/32, BB), 256, SMEM_BALL>>>(xyz, points, fps, out1);
    k_stats<<<592, 256, SMEM_STATS>>>(W1, g1, b1, W2, g2, b2);
    k_mma<<<NTILES, 256, SM_MMA_TOTAL>>>(W2, W3);
    k_out2<<<dim3(SS/32, BB), 256>>>(g3, b3, out2);
}